// round 9
// baseline (speedup 1.0000x reference)
#include <cuda_runtime.h>
#include <cuda_fp16.h>
#include <stdint.h>

// ---------------- problem constants ----------------
#define BATCH 16
#define SEQ   4096
#define FEAT  512
#define MROWS (BATCH*SEQ)          // 65536
#define M_CTA 64
#define NUM_CTAS (MROWS/M_CTA)     // 1024
#define THREADS 256
#define NKT 16                     // K slices of 32
#define NC 2                       // N halves of 256
#define NIT (NKT*NC)               // 32

// A tile: 64 rows x 32 f16, stride 80B/row (20 words -> conflict-free frag LDS)
#define A_TILE_B (M_CTA*80)        // 5120
#define B_TILE_B 16384             // 32k x 256n x 2B (fragment-major f16)

// smem layout (bytes)
#define OFF_U    0                 // 2048
#define OFF_BV   2048              // 2048
#define OFF_SRED 4096              // 4*64 floats = 1024
#define OFF_SE   5120              // 64 floats = 256
#define OFF_A0   5376
#define OFF_A1   (OFF_A0 + A_TILE_B)   // 10496
#define OFF_B0   (OFF_A1 + A_TILE_B)   // 15616
#define OFF_B1   (OFF_B0 + B_TILE_B)   // 32000
#define SMEM_TOTAL (OFF_B1 + B_TILE_B) // 48384  (x2 CTAs = 96768)

// ---------------- global scratch ----------------
__device__ uint4 g_Wfrag[32768];         // f16 fragment-major W (512 KB)
__device__ float g_part[NUM_CTAS];
__device__ float g_sumE;
__device__ float g_po[(size_t)NUM_CTAS*FEAT];

__device__ __forceinline__ uint32_t pack_f16x2(float lo, float hi) {
    __half2 h = __floats2half2_rn(lo, hi);
    return *(uint32_t*)&h;
}

__device__ __forceinline__ void mma_f16(float& d0, float& d1, float& d2, float& d3,
                                        uint32_t a0, uint32_t a1, uint32_t a2, uint32_t a3,
                                        uint32_t b0, uint32_t b1) {
    asm volatile(
        "mma.sync.aligned.m16n8k16.row.col.f32.f16.f16.f32 "
        "{%0,%1,%2,%3}, {%4,%5,%6,%7}, {%8,%9}, {%0,%1,%2,%3};"
        : "+f"(d0), "+f"(d1), "+f"(d2), "+f"(d3)
        : "r"(a0), "r"(a1), "r"(a2), "r"(a3), "r"(b0), "r"(b1));
}

__device__ __forceinline__ void cpa16(uint32_t dst, const void* src) {
    asm volatile("cp.async.cg.shared.global [%0], [%1], 16;" :: "r"(dst), "l"(src));
}

__device__ __forceinline__ uint32_t smem_u32(const void* p) {
    uint32_t a;
    asm("{ .reg .u64 t; cvta.to.shared.u64 t, %1; cvt.u32.u64 %0, t; }" : "=r"(a) : "l"(p));
    return a;
}

// fast tanh via 2 MUFU; rel err ~1e-6, saturates to +-1
__device__ __forceinline__ float ftanh(float v) {
    float t = __expf(2.0f * v);
    return 1.0f - __fdividef(2.0f, t + 1.0f);
}

// ---------------- k0: pack W -> f16 fragment-major ----------------
// uint4 g[idx], idx = ((kt*2+nc)*32 + ks*16 + wn*4 + ntp)*32 + lane  (32768 total)
// k  = kt*32 + ks*16 + 2*(lane&3)    np0 = nc*256 + wn*64 + ntp*16 + (lane>>2)
// v.x = {W[k][np0],   W[k+1][np0]}   v.y = {W[k+8][np0], W[k+9][np0]}
// v.z = {W[k][np0+8], W[k+1][np0+8]} v.w = {W[k+8][np0+8], W[k+9][np0+8]}
__global__ void k0_pack(const float* __restrict__ W) {
    int g = blockIdx.x * 256 + threadIdx.x;          // 0..32767
    int lane = g & 31;
    int t    = g >> 5;
    int ntp  = t & 3;
    int wn   = (t >> 2) & 3;
    int ks   = (t >> 4) & 1;
    int nc   = (t >> 5) & 1;
    int kt   = t >> 6;
    int k   = kt * 32 + ks * 16 + 2 * (lane & 3);
    int np0 = nc * 256 + wn * 64 + ntp * 16 + (lane >> 2);
    int np1 = np0 + 8;
    uint4 v;
    v.x = pack_f16x2(W[(size_t)k * FEAT + np0],       W[(size_t)(k + 1) * FEAT + np0]);
    v.y = pack_f16x2(W[(size_t)(k + 8) * FEAT + np0], W[(size_t)(k + 9) * FEAT + np0]);
    v.z = pack_f16x2(W[(size_t)k * FEAT + np1],       W[(size_t)(k + 1) * FEAT + np1]);
    v.w = pack_f16x2(W[(size_t)(k + 8) * FEAT + np1], W[(size_t)(k + 9) * FEAT + np1]);
    g_Wfrag[g] = v;
}

// ---------------- k1 helpers ----------------
// A prefetch: thread t covers row r = t>>2, quarter q = t&3 (8 floats)
__device__ __forceinline__ void ldg_A(float4 pa[2], const float* __restrict__ xg,
                                      int row0, int it, int tid) {
    const int kt = it & 15;
    const int r = tid >> 2, q = tid & 3;
    const float* src = xg + (size_t)(row0 + r) * FEAT + kt * 32 + q * 8;
    pa[0] = *(const float4*)(src);
    pa[1] = *(const float4*)(src + 4);
}

__device__ __forceinline__ void sts_A(const float4 pa[2], uint32_t a_s, int tid) {
    const int r = tid >> 2, q = tid & 3;
    uint4 h;
    h.x = pack_f16x2(pa[0].x, pa[0].y);
    h.y = pack_f16x2(pa[0].z, pa[0].w);
    h.z = pack_f16x2(pa[1].x, pa[1].y);
    h.w = pack_f16x2(pa[1].z, pa[1].w);
    *(uint4*)((char*)0 + 0, (void*)0), (void)0;   // (no-op; keep asm-free path)
    asm volatile("st.shared.v4.b32 [%0], {%1,%2,%3,%4};"
                 :: "r"(a_s + r * 80 + q * 16), "r"(h.x), "r"(h.y), "r"(h.z), "r"(h.w));
}

__device__ __forceinline__ void ldb_B(uint32_t b_s, int it, int tid) {
    const uint4* src = g_Wfrag + (size_t)(it) * 1024;   // slab (kt*2+nc) ordered by it? no:
    // it = nc*16 + kt, slab index = kt*2 + nc
    const int nc = it >> 4, kt = it & 15;
    src = g_Wfrag + (size_t)(kt * 2 + nc) * 1024;
    #pragma unroll
    for (int i = 0; i < 4; i++) {
        int id = tid + i * THREADS;
        cpa16(b_s + id * 16, (const char*)src + id * 16);
    }
    asm volatile("cp.async.commit_group;" ::: "memory");
}

__global__ __launch_bounds__(THREADS, 2)
void k1_gemm(const float* __restrict__ xg, const float* __restrict__ bg,
             const float* __restrict__ ug) {
    extern __shared__ char smem[];
    const uint32_t sbase = smem_u32(smem);
    const int tid  = threadIdx.x;
    const int lane = tid & 31;
    const int wid  = tid >> 5;
    const int wm   = wid & 1;        // 2 row groups of 32
    const int wn   = wid >> 1;       // 4 col groups of 64 (within 256-half)
    const int lr   = lane >> 2;
    const int lc   = lane & 3;
    const int row0 = blockIdx.x * M_CTA;

    float* usm  = (float*)(smem + OFF_U);
    float* bsm  = (float*)(smem + OFF_BV);
    float* sred = (float*)(smem + OFF_SRED);
    float* se_s = (float*)(smem + OFF_SE);

    #pragma unroll
    for (int i = 0; i < 2; i++) {
        usm[tid + i * THREADS] = ug[tid + i * THREADS];
        bsm[tid + i * THREADS] = bg[tid + i * THREADS];
    }

    const uint32_t a_s[2] = { sbase + OFF_A0, sbase + OFF_A1 };
    const uint32_t b_s[2] = { sbase + OFF_B0, sbase + OFF_B1 };

    // prologue: A0,A1 via LDG+cvt+STS; B0,B1 via cp.async
    {
        float4 pa[2];
        ldg_A(pa, xg, row0, 0, tid);
        sts_A(pa, a_s[0], tid);
        ldg_A(pa, xg, row0, 1, tid);
        sts_A(pa, a_s[1], tid);
    }
    ldb_B(b_s[0], 0, tid);
    ldb_B(b_s[1], 1, tid);

    // score partials: [mt][row-half]
    float sp[2][2] = {{0.f, 0.f}, {0.f, 0.f}};
    float4 pa[2];

    for (int nc = 0; nc < NC; nc++) {
        float acc[2][8][4];
        #pragma unroll
        for (int mt = 0; mt < 2; mt++)
            #pragma unroll
            for (int nt = 0; nt < 8; nt++)
                acc[mt][nt][0] = acc[mt][nt][1] = acc[mt][nt][2] = acc[mt][nt][3] = 0.0f;

        for (int kt = 0; kt < NKT; kt++) {
            const int it = nc * NKT + kt;

            // prefetch A(it+2) from gmem (latency covered by compute below)
            if (it + 2 < NIT) ldg_A(pa, xg, row0, it + 2, tid);

            if (it < NIT - 1)
                asm volatile("cp.async.wait_group 1;" ::: "memory");
            else
                asm volatile("cp.async.wait_group 0;" ::: "memory");
            __syncthreads();

            const uint32_t* Af = (const uint32_t*)(smem + ((it & 1) ? OFF_A1 : OFF_A0));
            const uint4*    Bf = (const uint4*)   (smem + ((it & 1) ? OFF_B1 : OFF_B0));

            #pragma unroll
            for (int ks = 0; ks < 2; ks++) {
                uint32_t a[2][4];
                #pragma unroll
                for (int mt = 0; mt < 2; mt++) {
                    const int ra = (wm * 32 + mt * 16 + lr) * 20 + ks * 8 + lc;
                    a[mt][0] = Af[ra];
                    a[mt][1] = Af[ra + 8 * 20];
                    a[mt][2] = Af[ra + 4];
                    a[mt][3] = Af[ra + 8 * 20 + 4];
                }
                #pragma unroll
                for (int ntp = 0; ntp < 4; ntp++) {
                    uint4 bb = Bf[(size_t)((ks * 16 + wn * 4 + ntp) * 32 + lane)];
                    #pragma unroll
                    for (int mt = 0; mt < 2; mt++) {
                        mma_f16(acc[mt][2*ntp][0], acc[mt][2*ntp][1],
                                acc[mt][2*ntp][2], acc[mt][2*ntp][3],
                                a[mt][0], a[mt][1], a[mt][2], a[mt][3], bb.x, bb.y);
                        mma_f16(acc[mt][2*ntp+1][0], acc[mt][2*ntp+1][1],
                                acc[mt][2*ntp+1][2], acc[mt][2*ntp+1][3],
                                a[mt][0], a[mt][1], a[mt][2], a[mt][3], bb.z, bb.w);
                    }
                }
            }

            if (it + 2 < NIT) {
                __syncthreads();   // all reads of buf (it&1) done
                sts_A(pa, a_s[it & 1], tid);
                ldb_B(b_s[it & 1], it + 2, tid);
            }
        }

        // epilogue for this n-half: tanh + dot(u), fixed order
        #pragma unroll
        for (int mt = 0; mt < 2; mt++) {
            #pragma unroll
            for (int nt = 0; nt < 8; nt++) {
                int n = nc * 256 + wn * 64 + nt * 8 + lc * 2;
                float u0 = usm[n], u1 = usm[n + 1];
                float b0 = bsm[n], b1 = bsm[n + 1];
                sp[mt][0] += ftanh(acc[mt][nt][0] + b0) * u0;
                sp[mt][0] += ftanh(acc[mt][nt][1] + b1) * u1;
                sp[mt][1] += ftanh(acc[mt][nt][2] + b0) * u0;
                sp[mt][1] += ftanh(acc[mt][nt][3] + b1) * u1;
            }
        }
    }

    // reduce over 4 lanes sharing a row (fixed order)
    #pragma unroll
    for (int mt = 0; mt < 2; mt++) {
        #pragma unroll
        for (int h = 0; h < 2; h++) {
            sp[mt][h] += __shfl_xor_sync(0xffffffffu, sp[mt][h], 1);
            sp[mt][h] += __shfl_xor_sync(0xffffffffu, sp[mt][h], 2);
        }
    }
    __syncthreads();
    if ((lane & 3) == 0) {
        #pragma unroll
        for (int mt = 0; mt < 2; mt++) {
            int r = wm * 32 + mt * 16 + lr;
            sred[wn * 64 + r]     = sp[mt][0];
            sred[wn * 64 + r + 8] = sp[mt][1];
        }
    }
    __syncthreads();

    if (tid < M_CTA) {
        float s = (sred[tid] + sred[64 + tid]) + (sred[128 + tid] + sred[192 + tid]);
        float e = expf(s);
        se_s[tid] = e;
        sred[tid] = e;
    }
    __syncthreads();
    #pragma unroll
    for (int off = 32; off > 0; off >>= 1) {
        if (tid < off) sred[tid] += sred[tid + off];
        __syncthreads();
    }
    if (tid == 0) g_part[blockIdx.x] = sred[0];

    // pooling partial: po[f] = sum_r x[row0+r][f] * e[r]   (fixed order, fp32 x)
    {
        const float* xb = xg + (size_t)row0 * FEAT;
        float p0 = 0.f, p1 = 0.f;
        #pragma unroll 4
        for (int r = 0; r < M_CTA; r++) {
            float ev = se_s[r];
            p0 += xb[(size_t)r * FEAT + tid]       * ev;
            p1 += xb[(size_t)r * FEAT + tid + 256] * ev;
        }
        g_po[(size_t)blockIdx.x * FEAT + tid]       = p0;
        g_po[(size_t)blockIdx.x * FEAT + tid + 256] = p1;
    }
}

// ---------------- k2: reduce 1024 partials ----------------
__global__ void k2_reduce() {
    __shared__ float red[512];
    int tid = threadIdx.x;
    red[tid] = g_part[tid] + g_part[tid + 512];
    __syncthreads();
    #pragma unroll
    for (int off = 256; off > 0; off >>= 1) {
        if (tid < off) red[tid] += red[tid + off];
        __syncthreads();
    }
    if (tid == 0) g_sumE = red[0];
}

// ---------------- k4: combine 64 CTA partials per batch + normalize ----------------
__global__ __launch_bounds__(512)
void k4_final(float* __restrict__ out) {
    int b = blockIdx.x, f = threadIdx.x;
    float s = 0.0f;
    #pragma unroll
    for (int c = 0; c < 64; c++)
        s += g_po[(size_t)(b * 64 + c) * FEAT + f];
    out[b * FEAT + f] = s / (g_sumE + 1e-7f);
}

extern "C" void kernel_launch(void* const* d_in, const int* in_sizes, int n_in,
                              void* d_out, int out_size) {
    const float* x = (const float*)d_in[0];
    const float* W = (const float*)d_in[1];
    const float* b = (const float*)d_in[2];
    const float* u = (const float*)d_in[3];
    float* out = (float*)d_out;

    cudaFuncSetAttribute(k1_gemm, cudaFuncAttributeMaxDynamicSharedMemorySize, SMEM_TOTAL);

    k0_pack<<<128, 256>>>(W);
    k1_gemm<<<NUM_CTAS, THREADS, SMEM_TOTAL>>>(x, b, u);
    k2_reduce<<<1, 512>>>();
    k4_final<<<BATCH, 512>>>(out);
}

// round 11
// speedup vs baseline: 1.2250x; 1.2250x over previous
#include <cuda_runtime.h>
#include <cuda_fp16.h>
#include <stdint.h>

// ---------------- problem constants ----------------
#define BATCH 16
#define SEQ   4096
#define FEAT  512
#define MROWS (BATCH*SEQ)          // 65536
#define M_CTA 64
#define NUM_CTAS (MROWS/M_CTA)     // 1024
#define THREADS 256
#define NKT 16                     // K slices of 32
#define NC 2                       // N halves of 256
#define NIT (NKT*NC)               // 32
#define STAGES 4

// A stage: 64 rows x 32 f16, stride 80B/row (20 words -> conflict-free frag LDS)
#define A_STAGE_B (M_CTA*80)       // 5120
#define B_STAGE_B 16384            // 32k x 256n x 2B (fragment-major f16)

// smem layout (bytes)
#define OFF_U    0                 // 2048
#define OFF_BV   2048              // 2048
#define OFF_SRED 4096              // 4*64 floats = 1024
#define OFF_SE   5120              // 64 floats = 256
#define OFF_A0   5376              // 4 stages x 5120 = 20480
#define OFF_B0   (OFF_A0 + STAGES*A_STAGE_B)      // 25856
#define SMEM_TOTAL (OFF_B0 + STAGES*B_STAGE_B)    // 91392 (x2 CTAs = 182784)

// ---------------- global scratch ----------------
__device__ uint4  g_Wfrag[32768];              // f16 fragment-major W (512 KB)
__device__ __half g_xh[(size_t)MROWS*FEAT];    // x pre-converted to f16 (64 MB)
__device__ float  g_part[NUM_CTAS];
__device__ float  g_sumE;
__device__ float  g_po[(size_t)NUM_CTAS*FEAT];

__device__ __forceinline__ uint32_t pack_f16x2(float lo, float hi) {
    __half2 h = __floats2half2_rn(lo, hi);
    return *(uint32_t*)&h;
}

__device__ __forceinline__ void mma_f16(float& d0, float& d1, float& d2, float& d3,
                                        uint32_t a0, uint32_t a1, uint32_t a2, uint32_t a3,
                                        uint32_t b0, uint32_t b1) {
    asm volatile(
        "mma.sync.aligned.m16n8k16.row.col.f32.f16.f16.f32 "
        "{%0,%1,%2,%3}, {%4,%5,%6,%7}, {%8,%9}, {%0,%1,%2,%3};"
        : "+f"(d0), "+f"(d1), "+f"(d2), "+f"(d3)
        : "r"(a0), "r"(a1), "r"(a2), "r"(a3), "r"(b0), "r"(b1));
}

__device__ __forceinline__ void cpa16(uint32_t dst, const void* src) {
    asm volatile("cp.async.cg.shared.global [%0], [%1], 16;" :: "r"(dst), "l"(src));
}

__device__ __forceinline__ uint32_t smem_u32(const void* p) {
    uint32_t a;
    asm("{ .reg .u64 t; cvta.to.shared.u64 t, %1; cvt.u32.u64 %0, t; }" : "=r"(a) : "l"(p));
    return a;
}

// fast tanh via 2 MUFU; rel err ~1e-6, saturates to +-1
__device__ __forceinline__ float ftanh(float v) {
    float t = __expf(2.0f * v);
    return 1.0f - __fdividef(2.0f, t + 1.0f);
}

// ---------------- k0: pack W -> f16 fragment-major (layout validated R9) ----------------
// uint4 g[idx], idx = ((kt*2+nc)*32 + ks*16 + wn*4 + ntp)*32 + lane  (32768 total)
__global__ void k0_pack(const float* __restrict__ W) {
    int g = blockIdx.x * 256 + threadIdx.x;          // 0..32767
    int lane = g & 31;
    int t    = g >> 5;
    int ntp  = t & 3;
    int wn   = (t >> 2) & 3;
    int ks   = (t >> 4) & 1;
    int nc   = (t >> 5) & 1;
    int kt   = t >> 6;
    int k   = kt * 32 + ks * 16 + 2 * (lane & 3);
    int np0 = nc * 256 + wn * 64 + ntp * 16 + (lane >> 2);
    int np1 = np0 + 8;
    uint4 v;
    v.x = pack_f16x2(W[(size_t)k * FEAT + np0],       W[(size_t)(k + 1) * FEAT + np0]);
    v.y = pack_f16x2(W[(size_t)(k + 8) * FEAT + np0], W[(size_t)(k + 9) * FEAT + np0]);
    v.z = pack_f16x2(W[(size_t)k * FEAT + np1],       W[(size_t)(k + 1) * FEAT + np1]);
    v.w = pack_f16x2(W[(size_t)(k + 8) * FEAT + np1], W[(size_t)(k + 9) * FEAT + np1]);
    g_Wfrag[g] = v;
}

// ---------------- k0b: convert x -> f16 ----------------
// Each thread converts 8 floats (2x float4 -> 1x uint4 of f16x2).
// 33554432 elems / 8 per thread = 4194304 threads = 16384 blocks x 256.
__global__ __launch_bounds__(256)
void k0b_xh(const float* __restrict__ x) {
    size_t g = (size_t)blockIdx.x * 256 + threadIdx.x;      // 0 .. 4194303
    const float4* src = (const float4*)x + g * 2;
    float4 v0 = src[0], v1 = src[1];
    uint4 h;
    h.x = pack_f16x2(v0.x, v0.y);
    h.y = pack_f16x2(v0.z, v0.w);
    h.z = pack_f16x2(v1.x, v1.y);
    h.w = pack_f16x2(v1.z, v1.w);
    ((uint4*)g_xh)[g] = h;
}

// ---------------- k1: 4-stage pipelined f16 mma GEMM + tanh + score + exp + pool ----------------
// load tile 'it' (nc = it>>4, kt = it&15) into stage buffer s
__device__ __forceinline__ void load_tile(uint32_t sbase, int s, int it,
                                          int row0, int tid) {
    const int nc = it >> 4, kt = it & 15;
    // A: g_xh[row0+r][kt*32 .. +32), 16B chunks (8 halves), 80B smem row stride
    {
        int r = tid >> 2, c = tid & 3;
        cpa16(sbase + OFF_A0 + s * A_STAGE_B + r * 80 + c * 16,
              g_xh + (size_t)(row0 + r) * FEAT + kt * 32 + c * 8);
    }
    // B: linear 16KB slab
    const char* src = (const char*)(g_Wfrag + (size_t)(kt * 2 + nc) * 1024);
    uint32_t bdst = sbase + OFF_B0 + s * B_STAGE_B;
    #pragma unroll
    for (int i = 0; i < 4; i++) {
        int id = tid + i * THREADS;
        cpa16(bdst + id * 16, src + id * 16);
    }
    asm volatile("cp.async.commit_group;" ::: "memory");
}

__global__ __launch_bounds__(THREADS, 2)
void k1_gemm(const float* __restrict__ xg, const float* __restrict__ bg,
             const float* __restrict__ ug) {
    extern __shared__ char smem[];
    const uint32_t sbase = smem_u32(smem);
    const int tid  = threadIdx.x;
    const int lane = tid & 31;
    const int wid  = tid >> 5;
    const int wm   = wid & 1;        // 2 row groups of 32
    const int wn   = wid >> 1;       // 4 col groups of 64 (within 256-half)
    const int lr   = lane >> 2;
    const int lc   = lane & 3;
    const int row0 = blockIdx.x * M_CTA;

    float* usm  = (float*)(smem + OFF_U);
    float* bsm  = (float*)(smem + OFF_BV);
    float* sred = (float*)(smem + OFF_SRED);
    float* se_s = (float*)(smem + OFF_SE);

    #pragma unroll
    for (int i = 0; i < 2; i++) {
        usm[tid + i * THREADS] = ug[tid + i * THREADS];
        bsm[tid + i * THREADS] = bg[tid + i * THREADS];
    }

    // prologue: stages 0..2 <- tiles 0..2
    load_tile(sbase, 0, 0, row0, tid);
    load_tile(sbase, 1, 1, row0, tid);
    load_tile(sbase, 2, 2, row0, tid);

    // score partials: [mt][row-half]
    float sp[2][2] = {{0.f, 0.f}, {0.f, 0.f}};

    for (int nc = 0; nc < NC; nc++) {
        float acc[2][8][4];
        #pragma unroll
        for (int mt = 0; mt < 2; mt++)
            #pragma unroll
            for (int nt = 0; nt < 8; nt++)
                acc[mt][nt][0] = acc[mt][nt][1] = acc[mt][nt][2] = acc[mt][nt][3] = 0.0f;

        for (int kt = 0; kt < NKT; kt++) {
            const int it = nc * NKT + kt;

            // tile 'it' guaranteed resident after this wait
            if (it < NIT - 2)
                asm volatile("cp.async.wait_group 2;" ::: "memory");
            else if (it == NIT - 2)
                asm volatile("cp.async.wait_group 1;" ::: "memory");
            else
                asm volatile("cp.async.wait_group 0;" ::: "memory");
            __syncthreads();

            // refill: tile it+3 into the buffer consumed at iter it-1
            if (it + 3 < NIT)
                load_tile(sbase, (it + 3) & 3, it + 3, row0, tid);

            const int s = it & 3;
            const uint32_t* Af = (const uint32_t*)(smem + OFF_A0 + s * A_STAGE_B);
            const uint4*    Bf = (const uint4*)   (smem + OFF_B0 + s * B_STAGE_B);

            #pragma unroll
            for (int ks = 0; ks < 2; ks++) {
                uint32_t a[2][4];
                #pragma unroll
                for (int mt = 0; mt < 2; mt++) {
                    const int ra = (wm * 32 + mt * 16 + lr) * 20 + ks * 8 + lc;
                    a[mt][0] = Af[ra];
                    a[mt][1] = Af[ra + 8 * 20];
                    a[mt][2] = Af[ra + 4];
                    a[mt][3] = Af[ra + 8 * 20 + 4];
                }
                #pragma unroll
                for (int ntp = 0; ntp < 4; ntp++) {
                    uint4 bb = Bf[(size_t)((ks * 16 + wn * 4 + ntp) * 32 + lane)];
                    #pragma unroll
                    for (int mt = 0; mt < 2; mt++) {
                        mma_f16(acc[mt][2*ntp][0], acc[mt][2*ntp][1],
                                acc[mt][2*ntp][2], acc[mt][2*ntp][3],
                                a[mt][0], a[mt][1], a[mt][2], a[mt][3], bb.x, bb.y);
                        mma_f16(acc[mt][2*ntp+1][0], acc[mt][2*ntp+1][1],
                                acc[mt][2*ntp+1][2], acc[mt][2*ntp+1][3],
                                a[mt][0], a[mt][1], a[mt][2], a[mt][3], bb.z, bb.w);
                    }
                }
            }
        }

        // epilogue for this n-half: tanh + dot(u), fixed order
        #pragma unroll
        for (int mt = 0; mt < 2; mt++) {
            #pragma unroll
            for (int nt = 0; nt < 8; nt++) {
                int n = nc * 256 + wn * 64 + nt * 8 + lc * 2;
                float u0 = usm[n], u1 = usm[n + 1];
                float b0 = bsm[n], b1 = bsm[n + 1];
                sp[mt][0] += ftanh(acc[mt][nt][0] + b0) * u0;
                sp[mt][0] += ftanh(acc[mt][nt][1] + b1) * u1;
                sp[mt][1] += ftanh(acc[mt][nt][2] + b0) * u0;
                sp[mt][1] += ftanh(acc[mt][nt][3] + b1) * u1;
            }
        }
    }

    // reduce over 4 lanes sharing a row (fixed order)
    #pragma unroll
    for (int mt = 0; mt < 2; mt++) {
        #pragma unroll
        for (int h = 0; h < 2; h++) {
            sp[mt][h] += __shfl_xor_sync(0xffffffffu, sp[mt][h], 1);
            sp[mt][h] += __shfl_xor_sync(0xffffffffu, sp[mt][h], 2);
        }
    }
    __syncthreads();
    if ((lane & 3) == 0) {
        #pragma unroll
        for (int mt = 0; mt < 2; mt++) {
            int r = wm * 32 + mt * 16 + lr;
            sred[wn * 64 + r]     = sp[mt][0];
            sred[wn * 64 + r + 8] = sp[mt][1];
        }
    }
    __syncthreads();

    if (tid < M_CTA) {
        float s = (sred[tid] + sred[64 + tid]) + (sred[128 + tid] + sred[192 + tid]);
        float e = expf(s);
        se_s[tid] = e;
        sred[tid] = e;
    }
    __syncthreads();
    #pragma unroll
    for (int off = 32; off > 0; off >>= 1) {
        if (tid < off) sred[tid] += sred[tid + off];
        __syncthreads();
    }
    if (tid == 0) g_part[blockIdx.x] = sred[0];

    // pooling partial: po[f] = sum_r x[row0+r][f] * e[r]   (fp32 x, fixed order)
    {
        const float* xb = xg + (size_t)row0 * FEAT;
        float p0 = 0.f, p1 = 0.f;
        #pragma unroll 4
        for (int r = 0; r < M_CTA; r++) {
            float ev = se_s[r];
            p0 += xb[(size_t)r * FEAT + tid]       * ev;
            p1 += xb[(size_t)r * FEAT + tid + 256] * ev;
        }
        g_po[(size_t)blockIdx.x * FEAT + tid]       = p0;
        g_po[(size_t)blockIdx.x * FEAT + tid + 256] = p1;
    }
}

// ---------------- k2: reduce 1024 partials ----------------
__global__ void k2_reduce() {
    __shared__ float red[512];
    int tid = threadIdx.x;
    red[tid] = g_part[tid] + g_part[tid + 512];
    __syncthreads();
    #pragma unroll
    for (int off = 256; off > 0; off >>= 1) {
        if (tid < off) red[tid] += red[tid + off];
        __syncthreads();
    }
    if (tid == 0) g_sumE = red[0];
}

// ---------------- k4: combine 64 CTA partials per batch + normalize ----------------
__global__ __launch_bounds__(512)
void k4_final(float* __restrict__ out) {
    int b = blockIdx.x, f = threadIdx.x;
    float s = 0.0f;
    #pragma unroll
    for (int c = 0; c < 64; c++)
        s += g_po[(size_t)(b * 64 + c) * FEAT + f];
    out[b * FEAT + f] = s / (g_sumE + 1e-7f);
}

extern "C" void kernel_launch(void* const* d_in, const int* in_sizes, int n_in,
                              void* d_out, int out_size) {
    const float* x = (const float*)d_in[0];
    const float* W = (const float*)d_in[1];
    const float* b = (const float*)d_in[2];
    const float* u = (const float*)d_in[3];
    float* out = (float*)d_out;

    cudaFuncSetAttribute(k1_gemm, cudaFuncAttributeMaxDynamicSharedMemorySize, SMEM_TOTAL);

    k0_pack<<<128, 256>>>(W);
    k0b_xh<<<16384, 256>>>(x);
    k1_gemm<<<NUM_CTAS, THREADS, SMEM_TOTAL>>>(x, b, u);
    k2_reduce<<<1, 512>>>();
    k4_final<<<BATCH, 512>>>(out);
}

// round 12
// speedup vs baseline: 1.6091x; 1.3135x over previous
#include <cuda_runtime.h>
#include <cuda_fp16.h>
#include <stdint.h>

// ---------------- problem constants ----------------
#define BATCH 16
#define SEQ   4096
#define FEAT  512
#define MROWS (BATCH*SEQ)          // 65536
#define M_CTA 64
#define NUM_CTAS (MROWS/M_CTA)     // 1024
#define THREADS 256
#define NKT 16                     // K slices of 32
#define NC 2                       // N halves of 256
#define NIT (NKT*NC)               // 32

#define B_STAGE_B 16384            // 32k x 256n x 2B (fragment-major f16)
#define A_BYTES   65536            // 64 rows x 512 f16 (1024B/row, XOR-swizzled)

// smem layout (bytes)
#define OFF_U    0                 // 2048
#define OFF_BV   2048              // 2048
#define OFF_SRED 4096              // 4*64 floats = 1024
#define OFF_SE   5120              // 64 floats = 256
#define OFF_A    5376              // 65536
#define OFF_B0   (OFF_A + A_BYTES)          // 70912
#define SMEM_TOTAL (OFF_B0 + 2*B_STAGE_B)   // 103680 (x2 CTAs = 207360)

// ---------------- global scratch ----------------
__device__ uint4  g_Wfrag[32768];              // f16 fragment-major W (512 KB)
__device__ float  g_part[NUM_CTAS];
__device__ float  g_sumE;
__device__ float  g_po[(size_t)NUM_CTAS*FEAT];

__device__ __forceinline__ uint32_t pack_f16x2(float lo, float hi) {
    __half2 h = __floats2half2_rn(lo, hi);
    return *(uint32_t*)&h;
}

__device__ __forceinline__ void mma_f16(float& d0, float& d1, float& d2, float& d3,
                                        uint32_t a0, uint32_t a1, uint32_t a2, uint32_t a3,
                                        uint32_t b0, uint32_t b1) {
    asm volatile(
        "mma.sync.aligned.m16n8k16.row.col.f32.f16.f16.f32 "
        "{%0,%1,%2,%3}, {%4,%5,%6,%7}, {%8,%9}, {%0,%1,%2,%3};"
        : "+f"(d0), "+f"(d1), "+f"(d2), "+f"(d3)
        : "r"(a0), "r"(a1), "r"(a2), "r"(a3), "r"(b0), "r"(b1));
}

__device__ __forceinline__ void cpa16(uint32_t dst, const void* src) {
    asm volatile("cp.async.cg.shared.global [%0], [%1], 16;" :: "r"(dst), "l"(src));
}

__device__ __forceinline__ uint32_t smem_u32(const void* p) {
    uint32_t a;
    asm("{ .reg .u64 t; cvta.to.shared.u64 t, %1; cvt.u32.u64 %0, t; }" : "=r"(a) : "l"(p));
    return a;
}

// fast tanh via 2 MUFU; rel err ~1e-6, saturates to +-1
__device__ __forceinline__ float ftanh(float v) {
    float t = __expf(2.0f * v);
    return 1.0f - __fdividef(2.0f, t + 1.0f);
}

// ---------------- k0: pack W -> f16 fragment-major (layout validated R9/R11) ----------------
// uint4 g[idx], idx = ((kt*2+nc)*32 + ks*16 + wn*4 + ntp)*32 + lane  (32768 total)
__global__ void k0_pack(const float* __restrict__ W) {
    int g = blockIdx.x * 256 + threadIdx.x;          // 0..32767
    int lane = g & 31;
    int t    = g >> 5;
    int ntp  = t & 3;
    int wn   = (t >> 2) & 3;
    int ks   = (t >> 4) & 1;
    int nc   = (t >> 5) & 1;
    int kt   = t >> 6;
    int k   = kt * 32 + ks * 16 + 2 * (lane & 3);
    int np0 = nc * 256 + wn * 64 + ntp * 16 + (lane >> 2);
    int np1 = np0 + 8;
    uint4 v;
    v.x = pack_f16x2(W[(size_t)k * FEAT + np0],       W[(size_t)(k + 1) * FEAT + np0]);
    v.y = pack_f16x2(W[(size_t)(k + 8) * FEAT + np0], W[(size_t)(k + 9) * FEAT + np0]);
    v.z = pack_f16x2(W[(size_t)k * FEAT + np1],       W[(size_t)(k + 1) * FEAT + np1]);
    v.w = pack_f16x2(W[(size_t)(k + 8) * FEAT + np1], W[(size_t)(k + 9) * FEAT + np1]);
    g_Wfrag[g] = v;
}

// ---------------- k1: A-resident f16 mma GEMM + tanh + score + exp + pool ----------------
// B slab loader: slab for tile it (nc=it>>4, kt=it&15) into given stage
__device__ __forceinline__ void load_B(uint32_t sbase, int stage, int it, int tid) {
    const int nc = it >> 4, kt = it & 15;
    const char* src = (const char*)(g_Wfrag + (size_t)(kt * 2 + nc) * 1024);
    uint32_t bdst = sbase + OFF_B0 + stage * B_STAGE_B;
    #pragma unroll
    for (int i = 0; i < 4; i++) {
        int id = tid + i * THREADS;
        cpa16(bdst + id * 16, src + id * 16);
    }
    asm volatile("cp.async.commit_group;" ::: "memory");
}

__global__ __launch_bounds__(THREADS, 2)
void k1_gemm(const float* __restrict__ xg, const float* __restrict__ bg,
             const float* __restrict__ ug) {
    extern __shared__ char smem[];
    const uint32_t sbase = smem_u32(smem);
    const int tid  = threadIdx.x;
    const int lane = tid & 31;
    const int wid  = tid >> 5;
    const int wm   = wid & 1;        // 2 row groups of 32
    const int wn   = wid >> 1;       // 4 col groups of 64 (within 256-half)
    const int lr   = lane >> 2;
    const int lc   = lane & 3;
    const int row0 = blockIdx.x * M_CTA;

    float* usm  = (float*)(smem + OFF_U);
    float* bsm  = (float*)(smem + OFF_BV);
    float* sred = (float*)(smem + OFF_SRED);
    float* se_s = (float*)(smem + OFF_SE);

    // start B slab 0 early (overlaps with A conversion)
    load_B(sbase, 0, 0, tid);

    #pragma unroll
    for (int i = 0; i < 2; i++) {
        usm[tid + i * THREADS] = ug[tid + i * THREADS];
        bsm[tid + i * THREADS] = bg[tid + i * THREADS];
    }

    // ---- A prologue: load 64x512 fp32 x-tile, convert to f16 smem (XOR swizzle) ----
    // word layout: row r (1024B), word w (0..255) stored at w ^ ((r&7)<<2)
    {
        uint32_t* As = (uint32_t*)(smem + OFF_A);
        #pragma unroll
        for (int i = 0; i < 32; i++) {
            int id = tid + i * THREADS;       // float4 index, 0..8191
            int r  = id >> 7;                 // 128 float4 per row
            int c4 = id & 127;
            float4 v = *(const float4*)(xg + (size_t)(row0 + r) * FEAT + c4 * 4);
            int w0 = c4 * 2;
            int sw = w0 ^ ((r & 7) << 2);     // bit0 of w0 is 0, XOR on bits2-4 keeps pair adjacent
            As[r * 256 + sw]     = pack_f16x2(v.x, v.y);
            As[r * 256 + sw + 1] = pack_f16x2(v.z, v.w);
        }
    }

    // score partials: [mt][row-half]
    float sp[2][2] = {{0.f, 0.f}, {0.f, 0.f}};
    const uint32_t* As = (const uint32_t*)(smem + OFF_A);
    const int swz = lr << 2;

    for (int nc = 0; nc < NC; nc++) {
        float acc[2][8][4];
        #pragma unroll
        for (int mt = 0; mt < 2; mt++)
            #pragma unroll
            for (int nt = 0; nt < 8; nt++)
                acc[mt][nt][0] = acc[mt][nt][1] = acc[mt][nt][2] = acc[mt][nt][3] = 0.0f;

        for (int kt = 0; kt < NKT; kt++) {
            const int it = nc * NKT + kt;

            // barrier: conversion done (it=0) / previous iter's reads of the other stage done
            __syncthreads();
            if (it + 1 < NIT) {
                load_B(sbase, (it + 1) & 1, it + 1, tid);   // refill freed stage
                asm volatile("cp.async.wait_group 1;" ::: "memory");   // slab 'it' resident
            } else {
                asm volatile("cp.async.wait_group 0;" ::: "memory");
            }

            const uint4* Bf = (const uint4*)(smem + OFF_B0 + (it & 1) * B_STAGE_B);

            #pragma unroll
            for (int ks = 0; ks < 2; ks++) {
                const int w = kt * 16 + ks * 8 + lc;
                uint32_t a[2][4];
                #pragma unroll
                for (int mt = 0; mt < 2; mt++) {
                    const int rb = (wm * 32 + mt * 16 + lr) * 256;
                    a[mt][0] = As[rb + (w ^ swz)];
                    a[mt][1] = As[rb + 8 * 256 + (w ^ swz)];
                    a[mt][2] = As[rb + ((w + 4) ^ swz)];
                    a[mt][3] = As[rb + 8 * 256 + ((w + 4) ^ swz)];
                }
                #pragma unroll
                for (int ntp = 0; ntp < 4; ntp++) {
                    uint4 bb = Bf[(size_t)((ks * 16 + wn * 4 + ntp) * 32 + lane)];
                    #pragma unroll
                    for (int mt = 0; mt < 2; mt++) {
                        mma_f16(acc[mt][2*ntp][0], acc[mt][2*ntp][1],
                                acc[mt][2*ntp][2], acc[mt][2*ntp][3],
                                a[mt][0], a[mt][1], a[mt][2], a[mt][3], bb.x, bb.y);
                        mma_f16(acc[mt][2*ntp+1][0], acc[mt][2*ntp+1][1],
                                acc[mt][2*ntp+1][2], acc[mt][2*ntp+1][3],
                                a[mt][0], a[mt][1], a[mt][2], a[mt][3], bb.z, bb.w);
                    }
                }
            }
        }

        // epilogue for this n-half: tanh + dot(u), fixed order
        #pragma unroll
        for (int mt = 0; mt < 2; mt++) {
            #pragma unroll
            for (int nt = 0; nt < 8; nt++) {
                int n = nc * 256 + wn * 64 + nt * 8 + lc * 2;
                float u0 = usm[n], u1 = usm[n + 1];
                float b0 = bsm[n], b1 = bsm[n + 1];
                sp[mt][0] += ftanh(acc[mt][nt][0] + b0) * u0;
                sp[mt][0] += ftanh(acc[mt][nt][1] + b1) * u1;
                sp[mt][1] += ftanh(acc[mt][nt][2] + b0) * u0;
                sp[mt][1] += ftanh(acc[mt][nt][3] + b1) * u1;
            }
        }
    }

    // reduce over 4 lanes sharing a row (fixed order)
    #pragma unroll
    for (int mt = 0; mt < 2; mt++) {
        #pragma unroll
        for (int h = 0; h < 2; h++) {
            sp[mt][h] += __shfl_xor_sync(0xffffffffu, sp[mt][h], 1);
            sp[mt][h] += __shfl_xor_sync(0xffffffffu, sp[mt][h], 2);
        }
    }
    __syncthreads();
    if ((lane & 3) == 0) {
        #pragma unroll
        for (int mt = 0; mt < 2; mt++) {
            int r = wm * 32 + mt * 16 + lr;
            sred[wn * 64 + r]     = sp[mt][0];
            sred[wn * 64 + r + 8] = sp[mt][1];
        }
    }
    __syncthreads();

    if (tid < M_CTA) {
        float s = (sred[tid] + sred[64 + tid]) + (sred[128 + tid] + sred[192 + tid]);
        float e = expf(s);
        se_s[tid] = e;
        sred[tid] = e;
    }
    __syncthreads();
    #pragma unroll
    for (int off = 32; off > 0; off >>= 1) {
        if (tid < off) sred[tid] += sred[tid + off];
        __syncthreads();
    }
    if (tid == 0) g_part[blockIdx.x] = sred[0];

    // pooling partial from f16 A smem: po[f] = sum_r x[r][f]*e[r]
    // thread covers f0 = 2*tid, f1 = 2*tid+1  (word w = tid, same swizzle)
    {
        float p0 = 0.f, p1 = 0.f;
        #pragma unroll 4
        for (int r = 0; r < M_CTA; r++) {
            uint32_t hw = As[r * 256 + (tid ^ ((r & 7) << 2))];
            float2 xf = __half22float2(*(__half2*)&hw);
            float ev = se_s[r];
            p0 += xf.x * ev;
            p1 += xf.y * ev;
        }
        float2* po = (float2*)(g_po + (size_t)blockIdx.x * FEAT);
        po[tid] = make_float2(p0, p1);
    }
}

// ---------------- k2: reduce 1024 partials ----------------
__global__ void k2_reduce() {
    __shared__ float red[512];
    int tid = threadIdx.x;
    red[tid] = g_part[tid] + g_part[tid + 512];
    __syncthreads();
    #pragma unroll
    for (int off = 256; off > 0; off >>= 1) {
        if (tid < off) red[tid] += red[tid + off];
        __syncthreads();
    }
    if (tid == 0) g_sumE = red[0];
}

// ---------------- k4: combine 64 CTA partials per batch + normalize ----------------
__global__ __launch_bounds__(512)
void k4_final(float* __restrict__ out) {
    int b = blockIdx.x, f = threadIdx.x;
    float s = 0.0f;
    #pragma unroll
    for (int c = 0; c < 64; c++)
        s += g_po[(size_t)(b * 64 + c) * FEAT + f];
    out[b * FEAT + f] = s / (g_sumE + 1e-7f);
}

extern "C" void kernel_launch(void* const* d_in, const int* in_sizes, int n_in,
                              void* d_out, int out_size) {
    const float* x = (const float*)d_in[0];
    const float* W = (const float*)d_in[1];
    const float* b = (const float*)d_in[2];
    const float* u = (const float*)d_in[3];
    float* out = (float*)d_out;

    cudaFuncSetAttribute(k1_gemm, cudaFuncAttributeMaxDynamicSharedMemorySize, SMEM_TOTAL);

    k0_pack<<<128, 256>>>(W);
    k1_gemm<<<NUM_CTAS, THREADS, SMEM_TOTAL>>>(x, b, u);
    k2_reduce<<<1, 512>>>();
    k4_final<<<BATCH, 512>>>(out);
}

// round 13
// speedup vs baseline: 1.6970x; 1.0546x over previous
#include <cuda_runtime.h>
#include <cuda_fp16.h>
#include <stdint.h>

// ---------------- problem constants ----------------
#define BATCH 16
#define SEQ   4096
#define FEAT  512
#define MROWS (BATCH*SEQ)          // 65536
#define M_CTA 64
#define NUM_CTAS (MROWS/M_CTA)     // 1024
#define THREADS 256
#define NKT 16                     // K slices of 32
#define NC 2                       // N halves of 256
#define NIT (NKT*NC)               // 32

#define B_STAGE_B 16384            // 32k x 256n x 2B (fragment-major f16)
#define A_BYTES   65536            // 64 rows x 512 f16 (1024B/row, XOR-swizzled)

// smem layout (bytes)
#define OFF_U    0                 // 2048
#define OFF_BV   2048              // 2048
#define OFF_SRED 4096              // 4*64 floats = 1024
#define OFF_SE   5120              // 64 floats = 256
#define OFF_A    5376              // 65536
#define OFF_B0   (OFF_A + A_BYTES)          // 70912
#define SMEM_TOTAL (OFF_B0 + 2*B_STAGE_B)   // 103680 (x2 CTAs = 207360)

// ---------------- global scratch ----------------
__device__ uint4  g_Wfrag[32768];              // f16 fragment-major W (512 KB)
__device__ float  g_part[NUM_CTAS];
__device__ float  g_po[(size_t)NUM_CTAS*FEAT];

__device__ __forceinline__ uint32_t pack_f16x2(float lo, float hi) {
    __half2 h = __floats2half2_rn(lo, hi);
    return *(uint32_t*)&h;
}

__device__ __forceinline__ void mma_f16(float& d0, float& d1, float& d2, float& d3,
                                        uint32_t a0, uint32_t a1, uint32_t a2, uint32_t a3,
                                        uint32_t b0, uint32_t b1) {
    asm volatile(
        "mma.sync.aligned.m16n8k16.row.col.f32.f16.f16.f32 "
        "{%0,%1,%2,%3}, {%4,%5,%6,%7}, {%8,%9}, {%0,%1,%2,%3};"
        : "+f"(d0), "+f"(d1), "+f"(d2), "+f"(d3)
        : "r"(a0), "r"(a1), "r"(a2), "r"(a3), "r"(b0), "r"(b1));
}

__device__ __forceinline__ void ldsm_x4(uint32_t& r0, uint32_t& r1, uint32_t& r2, uint32_t& r3,
                                        uint32_t addr) {
    asm volatile("ldmatrix.sync.aligned.m8n8.x4.shared.b16 {%0,%1,%2,%3}, [%4];"
                 : "=r"(r0), "=r"(r1), "=r"(r2), "=r"(r3) : "r"(addr));
}

__device__ __forceinline__ void cpa16(uint32_t dst, const void* src) {
    asm volatile("cp.async.cg.shared.global [%0], [%1], 16;" :: "r"(dst), "l"(src));
}

__device__ __forceinline__ uint32_t smem_u32(const void* p) {
    uint32_t a;
    asm("{ .reg .u64 t; cvta.to.shared.u64 t, %1; cvt.u32.u64 %0, t; }" : "=r"(a) : "l"(p));
    return a;
}

// fast tanh via 2 MUFU; rel err ~1e-6, saturates to +-1
__device__ __forceinline__ float ftanh(float v) {
    float t = __expf(2.0f * v);
    return 1.0f - __fdividef(2.0f, t + 1.0f);
}

// ---------------- k0: pack W -> f16 fragment-major (layout validated R9-R12) ----------------
// uint4 g[idx], idx = ((kt*2+nc)*32 + ks*16 + wn*4 + ntp)*32 + lane  (32768 total)
__global__ void k0_pack(const float* __restrict__ W) {
    int g = blockIdx.x * 256 + threadIdx.x;          // 0..32767
    int lane = g & 31;
    int t    = g >> 5;
    int ntp  = t & 3;
    int wn   = (t >> 2) & 3;
    int ks   = (t >> 4) & 1;
    int nc   = (t >> 5) & 1;
    int kt   = t >> 6;
    int k   = kt * 32 + ks * 16 + 2 * (lane & 3);
    int np0 = nc * 256 + wn * 64 + ntp * 16 + (lane >> 2);
    int np1 = np0 + 8;
    uint4 v;
    v.x = pack_f16x2(W[(size_t)k * FEAT + np0],       W[(size_t)(k + 1) * FEAT + np0]);
    v.y = pack_f16x2(W[(size_t)(k + 8) * FEAT + np0], W[(size_t)(k + 9) * FEAT + np0]);
    v.z = pack_f16x2(W[(size_t)k * FEAT + np1],       W[(size_t)(k + 1) * FEAT + np1]);
    v.w = pack_f16x2(W[(size_t)(k + 8) * FEAT + np1], W[(size_t)(k + 9) * FEAT + np1]);
    g_Wfrag[g] = v;
}

// ---------------- k1: A-resident f16 mma GEMM + tanh + score + exp + pool ----------------
// B slab loader: slab for tile it (nc=it>>4, kt=it&15) into given stage
__device__ __forceinline__ void load_B(uint32_t sbase, int stage, int it, int tid) {
    const int nc = it >> 4, kt = it & 15;
    const char* src = (const char*)(g_Wfrag + (size_t)(kt * 2 + nc) * 1024);
    uint32_t bdst = sbase + OFF_B0 + stage * B_STAGE_B;
    #pragma unroll
    for (int i = 0; i < 4; i++) {
        int id = tid + i * THREADS;
        cpa16(bdst + id * 16, src + id * 16);
    }
    asm volatile("cp.async.commit_group;" ::: "memory");
}

__global__ __launch_bounds__(THREADS, 2)
void k1_gemm(const float* __restrict__ xg, const float* __restrict__ bg,
             const float* __restrict__ ug) {
    extern __shared__ char smem[];
    const uint32_t sbase = smem_u32(smem);
    const int tid  = threadIdx.x;
    const int lane = tid & 31;
    const int wid  = tid >> 5;
    const int wm   = wid & 1;        // 2 row groups of 32
    const int wn   = wid >> 1;       // 4 col groups of 64 (within 256-half)
    const int lr   = lane >> 2;
    const int lc   = lane & 3;
    const int row0 = blockIdx.x * M_CTA;

    float* usm  = (float*)(smem + OFF_U);
    float* bsm  = (float*)(smem + OFF_BV);
    float* sred = (float*)(smem + OFF_SRED);
    float* se_s = (float*)(smem + OFF_SE);

    // start B slab 0 early (overlaps with A conversion)
    load_B(sbase, 0, 0, tid);

    #pragma unroll
    for (int i = 0; i < 2; i++) {
        usm[tid + i * THREADS] = ug[tid + i * THREADS];
        bsm[tid + i * THREADS] = bg[tid + i * THREADS];
    }

    // ---- A prologue: load 64x512 fp32 x-tile, convert to f16 smem (XOR swizzle) ----
    // word layout: row r (1024B = 256 words), word w stored at w ^ ((r&7)<<2)
    {
        uint32_t* As = (uint32_t*)(smem + OFF_A);
        #pragma unroll
        for (int i = 0; i < 32; i++) {
            int id = tid + i * THREADS;       // float4 index, 0..8191
            int r  = id >> 7;                 // 128 float4 per row
            int c4 = id & 127;
            float4 v = *(const float4*)(xg + (size_t)(row0 + r) * FEAT + c4 * 4);
            int w0 = c4 * 2;
            int sw = w0 ^ ((r & 7) << 2);     // XOR on bits2-4 keeps word pair adjacent
            As[r * 256 + sw]     = pack_f16x2(v.x, v.y);
            As[r * 256 + sw + 1] = pack_f16x2(v.z, v.w);
        }
    }

    // ldmatrix per-lane address components (matrix j, row-in-matrix rj)
    const int j   = lane >> 3;          // 0..3
    const int rj  = lane & 7;
    const int rowj = wm * 32 + (j & 1) * 8 + rj;   // (+ mt*16 via +16KB)
    const int cj  = (j >> 1) * 4;       // k-word offset for k8-15 matrices
    const int sj  = rj << 2;            // per-lane swizzle
    const uint32_t A0 = sbase + OFF_A;

    // score partials: [mt][row-half]
    float sp[2][2] = {{0.f, 0.f}, {0.f, 0.f}};
    const uint32_t* As = (const uint32_t*)(smem + OFF_A);

    for (int nc = 0; nc < NC; nc++) {
        float acc[2][8][4];
        #pragma unroll
        for (int mt = 0; mt < 2; mt++)
            #pragma unroll
            for (int nt = 0; nt < 8; nt++)
                acc[mt][nt][0] = acc[mt][nt][1] = acc[mt][nt][2] = acc[mt][nt][3] = 0.0f;

        for (int kt = 0; kt < NKT; kt++) {
            const int it = nc * NKT + kt;

            // barrier: conversion done (it=0) / previous iter's reads of the other stage done
            __syncthreads();
            if (it + 1 < NIT) {
                load_B(sbase, (it + 1) & 1, it + 1, tid);   // refill freed stage
                asm volatile("cp.async.wait_group 1;" ::: "memory");   // slab 'it' resident
            } else {
                asm volatile("cp.async.wait_group 0;" ::: "memory");
            }

            const uint4* Bf = (const uint4*)(smem + OFF_B0 + (it & 1) * B_STAGE_B);
            // per-lane ldmatrix base word for this kt (ks=0, mt=0)
            const uint32_t wordbase = rowj * 256 + (((kt * 16) | cj) ^ sj);

            #pragma unroll
            for (int ks = 0; ks < 2; ks++) {
                const uint32_t wks = wordbase ^ (ks << 3);
                uint32_t a[2][4];
                #pragma unroll
                for (int mt = 0; mt < 2; mt++)
                    ldsm_x4(a[mt][0], a[mt][1], a[mt][2], a[mt][3],
                            A0 + mt * 16384 + (wks << 2));
                #pragma unroll
                for (int ntp = 0; ntp < 4; ntp++) {
                    uint4 bb = Bf[(size_t)((ks * 16 + wn * 4 + ntp) * 32 + lane)];
                    #pragma unroll
                    for (int mt = 0; mt < 2; mt++) {
                        mma_f16(acc[mt][2*ntp][0], acc[mt][2*ntp][1],
                                acc[mt][2*ntp][2], acc[mt][2*ntp][3],
                                a[mt][0], a[mt][1], a[mt][2], a[mt][3], bb.x, bb.y);
                        mma_f16(acc[mt][2*ntp+1][0], acc[mt][2*ntp+1][1],
                                acc[mt][2*ntp+1][2], acc[mt][2*ntp+1][3],
                                a[mt][0], a[mt][1], a[mt][2], a[mt][3], bb.z, bb.w);
                    }
                }
            }
        }

        // epilogue for this n-half: tanh + dot(u), fixed order
        #pragma unroll
        for (int mt = 0; mt < 2; mt++) {
            #pragma unroll
            for (int nt = 0; nt < 8; nt++) {
                int n = nc * 256 + wn * 64 + nt * 8 + lc * 2;
                float u0 = usm[n], u1 = usm[n + 1];
                float b0 = bsm[n], b1 = bsm[n + 1];
                sp[mt][0] += ftanh(acc[mt][nt][0] + b0) * u0;
                sp[mt][0] += ftanh(acc[mt][nt][1] + b1) * u1;
                sp[mt][1] += ftanh(acc[mt][nt][2] + b0) * u0;
                sp[mt][1] += ftanh(acc[mt][nt][3] + b1) * u1;
            }
        }
    }

    // reduce over 4 lanes sharing a row (fixed order)
    #pragma unroll
    for (int mt = 0; mt < 2; mt++) {
        #pragma unroll
        for (int h = 0; h < 2; h++) {
            sp[mt][h] += __shfl_xor_sync(0xffffffffu, sp[mt][h], 1);
            sp[mt][h] += __shfl_xor_sync(0xffffffffu, sp[mt][h], 2);
        }
    }
    __syncthreads();
    if ((lane & 3) == 0) {
        #pragma unroll
        for (int mt = 0; mt < 2; mt++) {
            int r = wm * 32 + mt * 16 + lr;
            sred[wn * 64 + r]     = sp[mt][0];
            sred[wn * 64 + r + 8] = sp[mt][1];
        }
    }
    __syncthreads();

    if (tid < M_CTA) {
        float s = (sred[tid] + sred[64 + tid]) + (sred[128 + tid] + sred[192 + tid]);
        float e = expf(s);
        se_s[tid] = e;
        sred[tid] = e;
    }
    __syncthreads();
    #pragma unroll
    for (int off = 32; off > 0; off >>= 1) {
        if (tid < off) sred[tid] += sred[tid + off];
        __syncthreads();
    }
    if (tid == 0) g_part[blockIdx.x] = sred[0];

    // pooling partial from f16 A smem: po[f] = sum_r x[r][f]*e[r]
    // thread covers f0 = 2*tid, f1 = 2*tid+1  (word w = tid, same swizzle)
    {
        float p0 = 0.f, p1 = 0.f;
        #pragma unroll 4
        for (int r = 0; r < M_CTA; r++) {
            uint32_t hw = As[r * 256 + (tid ^ ((r & 7) << 2))];
            float2 xf = __half22float2(*(__half2*)&hw);
            float ev = se_s[r];
            p0 += xf.x * ev;
            p1 += xf.y * ev;
        }
        float2* po = (float2*)(g_po + (size_t)blockIdx.x * FEAT);
        po[tid] = make_float2(p0, p1);
    }
}

// ---------------- k4: global-sum + combine + normalize (k2 folded in) ----------------
// grid (4, BATCH), 128 threads. Every block redundantly reduces g_part (identical
// fixed order -> deterministic identical sumE), then combines its 128-feature slice.
__global__ __launch_bounds__(128)
void k4_final(float* __restrict__ out) {
    __shared__ float red[128];
    const int tid = threadIdx.x;
    const int b = blockIdx.y, q = blockIdx.x;

    float v = 0.0f;
    #pragma unroll
    for (int i = 0; i < 8; i++)
        v += g_part[tid * 8 + i];
    red[tid] = v;
    __syncthreads();
    #pragma unroll
    for (int off = 64; off > 0; off >>= 1) {
        if (tid < off) red[tid] += red[tid + off];
        __syncthreads();
    }
    const float denom = red[0] + 1e-7f;

    const int f = q * 128 + tid;
    float s = 0.0f;
    #pragma unroll
    for (int c = 0; c < 64; c++)
        s += g_po[(size_t)(b * 64 + c) * FEAT + f];
    out[b * FEAT + f] = s / denom;
}

extern "C" void kernel_launch(void* const* d_in, const int* in_sizes, int n_in,
                              void* d_out, int out_size) {
    const float* x = (const float*)d_in[0];
    const float* W = (const float*)d_in[1];
    const float* b = (const float*)d_in[2];
    const float* u = (const float*)d_in[3];
    float* out = (float*)d_out;

    cudaFuncSetAttribute(k1_gemm, cudaFuncAttributeMaxDynamicSharedMemorySize, SMEM_TOTAL);

    k0_pack<<<128, 256>>>(W);
    k1_gemm<<<NUM_CTAS, THREADS, SMEM_TOTAL>>>(x, b, u);
    k4_final<<<dim3(4, BATCH), 128>>>(out);
}

// round 14
// speedup vs baseline: 1.7124x; 1.0091x over previous
#include <cuda_runtime.h>
#include <cuda_fp16.h>
#include <stdint.h>

// ---------------- problem constants ----------------
#define BATCH 16
#define SEQ   4096
#define FEAT  512
#define MROWS (BATCH*SEQ)          // 65536
#define M_CTA 64
#define NUM_CTAS (MROWS/M_CTA)     // 1024
#define THREADS 256
#define NKT 16                     // K slices of 32
#define NC 2                       // N halves of 256
#define NIT (NKT*NC)               // 32

#define B_STAGE_B 16384            // 32k x 256n x 2B (fragment-major f16)
#define A_BYTES   65536            // 64 rows x 512 f16 (1024B/row, XOR-swizzled)

// smem layout (bytes)
#define OFF_U    0                 // 2048
#define OFF_BV   2048              // 2048
#define OFF_SRED 4096              // 4*64 floats = 1024
#define OFF_SE   5120              // 64 floats = 256
#define OFF_A    5376              // 65536
#define OFF_B0   (OFF_A + A_BYTES)          // 70912
#define SMEM_TOTAL (OFF_B0 + 2*B_STAGE_B)   // 103680 (x2 CTAs = 207360)

// ---------------- global scratch ----------------
__device__ uint4  g_Wfrag[32768];              // f16 fragment-major W (512 KB)
__device__ float  g_part[NUM_CTAS];
__device__ float  g_po[(size_t)NUM_CTAS*FEAT];

__device__ __forceinline__ uint32_t pack_f16x2(float lo, float hi) {
    __half2 h = __floats2half2_rn(lo, hi);
    return *(uint32_t*)&h;
}

__device__ __forceinline__ void mma_f16(float& d0, float& d1, float& d2, float& d3,
                                        uint32_t a0, uint32_t a1, uint32_t a2, uint32_t a3,
                                        uint32_t b0, uint32_t b1) {
    asm volatile(
        "mma.sync.aligned.m16n8k16.row.col.f32.f16.f16.f32 "
        "{%0,%1,%2,%3}, {%4,%5,%6,%7}, {%8,%9}, {%0,%1,%2,%3};"
        : "+f"(d0), "+f"(d1), "+f"(d2), "+f"(d3)
        : "r"(a0), "r"(a1), "r"(a2), "r"(a3), "r"(b0), "r"(b1));
}

__device__ __forceinline__ void ldsm_x4(uint32_t& r0, uint32_t& r1, uint32_t& r2, uint32_t& r3,
                                        uint32_t addr) {
    asm volatile("ldmatrix.sync.aligned.m8n8.x4.shared.b16 {%0,%1,%2,%3}, [%4];"
                 : "=r"(r0), "=r"(r1), "=r"(r2), "=r"(r3) : "r"(addr));
}

__device__ __forceinline__ void cpa16(uint32_t dst, const void* src) {
    asm volatile("cp.async.cg.shared.global [%0], [%1], 16;" :: "r"(dst), "l"(src));
}

__device__ __forceinline__ uint32_t smem_u32(const void* p) {
    uint32_t a;
    asm("{ .reg .u64 t; cvta.to.shared.u64 t, %1; cvt.u32.u64 %0, t; }" : "=r"(a) : "l"(p));
    return a;
}

// fast tanh via 2 MUFU; rel err ~1e-6, saturates to +-1
__device__ __forceinline__ float ftanh(float v) {
    float t = __expf(2.0f * v);
    return 1.0f - __fdividef(2.0f, t + 1.0f);
}

// ---------------- k0: pack W -> f16 fragment-major, smem-staged ----------------
// Produces byte-identical g_Wfrag to the R9-R13 validated layout:
//   g = kt*2048 + nc*1024 + ks*512 + wn*128 + ntp*32 + lane
//   k = kt*32 + ks*16 + 2*(lane&3); np0 = nc*256 + wn*64 + ntp*16 + (lane>>2)
// Block b: kt = b>>2, nc = (b>>1)&1, ks = b&1. Stages W rows [kt*32+ks*16, +16)
// cols [nc*256, +256) coalesced into padded smem (stride 260 words).
__global__ __launch_bounds__(256)
void k0_pack(const float* __restrict__ W) {
    __shared__ float ws[16 * 260];
    const int tid = threadIdx.x;
    const int kt = blockIdx.x >> 2;
    const int nc = (blockIdx.x >> 1) & 1;
    const int ks = blockIdx.x & 1;
    const int krow0 = kt * 32 + ks * 16;
    const int ncol0 = nc * 256;

    // coalesced load: 16 rows x 256 cols = 1024 float4
    #pragma unroll
    for (int i = 0; i < 4; i++) {
        int id = tid + i * 256;          // float4 idx
        int r = id >> 6, c4 = id & 63;
        float4 v = *(const float4*)(W + (size_t)(krow0 + r) * FEAT + ncol0 + c4 * 4);
        *(float4*)(ws + r * 260 + c4 * 4) = v;   // 1040B row stride: 16B aligned
    }
    __syncthreads();

    // emit 512 uint4, coalesced writes
    #pragma unroll
    for (int i = 0; i < 2; i++) {
        int local = tid + i * 256;       // 0..511
        int lane = local & 31;
        int tt   = local >> 5;           // 0..15
        int ntp  = tt & 3;
        int wn   = tt >> 2;
        int kl   = 2 * (lane & 3);
        int np   = wn * 64 + ntp * 16 + (lane >> 2);
        uint4 v;
        v.x = pack_f16x2(ws[kl * 260 + np],           ws[(kl + 1) * 260 + np]);
        v.y = pack_f16x2(ws[(kl + 8) * 260 + np],     ws[(kl + 9) * 260 + np]);
        v.z = pack_f16x2(ws[kl * 260 + np + 8],       ws[(kl + 1) * 260 + np + 8]);
        v.w = pack_f16x2(ws[(kl + 8) * 260 + np + 8], ws[(kl + 9) * 260 + np + 8]);
        g_Wfrag[kt * 2048 + nc * 1024 + ks * 512 + local] = v;
    }
}

// ---------------- k1: A-resident f16 mma GEMM + tanh + score + exp + pool ----------------
__device__ __forceinline__ void load_B(uint32_t sbase, int stage, int it, int tid) {
    const int nc = it >> 4, kt = it & 15;
    const char* src = (const char*)(g_Wfrag + (size_t)(kt * 2 + nc) * 1024);
    uint32_t bdst = sbase + OFF_B0 + stage * B_STAGE_B;
    #pragma unroll
    for (int i = 0; i < 4; i++) {
        int id = tid + i * THREADS;
        cpa16(bdst + id * 16, src + id * 16);
    }
    asm volatile("cp.async.commit_group;" ::: "memory");
}

__global__ __launch_bounds__(THREADS, 2)
void k1_gemm(const float* __restrict__ xg, const float* __restrict__ bg,
             const float* __restrict__ ug) {
    extern __shared__ char smem[];
    const uint32_t sbase = smem_u32(smem);
    const int tid  = threadIdx.x;
    const int lane = tid & 31;
    const int wid  = tid >> 5;
    const int wm   = wid & 1;        // 2 row groups of 32
    const int wn   = wid >> 1;       // 4 col groups of 64 (within 256-half)
    const int lr   = lane >> 2;
    const int lc   = lane & 3;
    const int row0 = blockIdx.x * M_CTA;

    float* usm  = (float*)(smem + OFF_U);
    float* bsm  = (float*)(smem + OFF_BV);
    float* sred = (float*)(smem + OFF_SRED);
    float* se_s = (float*)(smem + OFF_SE);

    // start B slab 0 early (overlaps with A conversion)
    load_B(sbase, 0, 0, tid);

    #pragma unroll
    for (int i = 0; i < 2; i++) {
        usm[tid + i * THREADS] = ug[tid + i * THREADS];
        bsm[tid + i * THREADS] = bg[tid + i * THREADS];
    }

    // ---- A prologue: load 64x512 fp32 x-tile, convert to f16 smem (XOR swizzle) ----
    {
        uint32_t* As = (uint32_t*)(smem + OFF_A);
        #pragma unroll
        for (int i = 0; i < 32; i++) {
            int id = tid + i * THREADS;       // float4 index, 0..8191
            int r  = id >> 7;
            int c4 = id & 127;
            float4 v = *(const float4*)(xg + (size_t)(row0 + r) * FEAT + c4 * 4);
            int w0 = c4 * 2;
            int sw = w0 ^ ((r & 7) << 2);
            As[r * 256 + sw]     = pack_f16x2(v.x, v.y);
            As[r * 256 + sw + 1] = pack_f16x2(v.z, v.w);
        }
    }

    // ldmatrix per-lane address components
    const int j    = lane >> 3;
    const int rj   = lane & 7;
    const int rowj = wm * 32 + (j & 1) * 8 + rj;
    const int cj   = (j >> 1) * 4;
    const int sj   = rj << 2;
    const uint32_t A0 = sbase + OFF_A;

    float sp[2][2] = {{0.f, 0.f}, {0.f, 0.f}};
    const uint32_t* As = (const uint32_t*)(smem + OFF_A);

    for (int nc = 0; nc < NC; nc++) {
        float acc[2][8][4];
        #pragma unroll
        for (int mt = 0; mt < 2; mt++)
            #pragma unroll
            for (int nt = 0; nt < 8; nt++)
                acc[mt][nt][0] = acc[mt][nt][1] = acc[mt][nt][2] = acc[mt][nt][3] = 0.0f;

        for (int kt = 0; kt < NKT; kt++) {
            const int it = nc * NKT + kt;

            __syncthreads();
            if (it + 1 < NIT) {
                load_B(sbase, (it + 1) & 1, it + 1, tid);
                asm volatile("cp.async.wait_group 1;" ::: "memory");
            } else {
                asm volatile("cp.async.wait_group 0;" ::: "memory");
            }

            const uint4* Bf = (const uint4*)(smem + OFF_B0 + (it & 1) * B_STAGE_B);
            const uint32_t wordbase = rowj * 256 + (((kt * 16) | cj) ^ sj);

            // hoist all A fragment loads (both ks) before any MMA
            uint32_t a[2][2][4];   // [ks][mt][4]
            #pragma unroll
            for (int ks = 0; ks < 2; ks++) {
                const uint32_t wks = wordbase ^ (ks << 3);
                #pragma unroll
                for (int mt = 0; mt < 2; mt++)
                    ldsm_x4(a[ks][mt][0], a[ks][mt][1], a[ks][mt][2], a[ks][mt][3],
                            A0 + mt * 16384 + (wks << 2));
            }

            #pragma unroll
            for (int ks = 0; ks < 2; ks++) {
                #pragma unroll
                for (int ntp = 0; ntp < 4; ntp++) {
                    uint4 bb = Bf[(size_t)((ks * 16 + wn * 4 + ntp) * 32 + lane)];
                    #pragma unroll
                    for (int mt = 0; mt < 2; mt++) {
                        mma_f16(acc[mt][2*ntp][0], acc[mt][2*ntp][1],
                                acc[mt][2*ntp][2], acc[mt][2*ntp][3],
                                a[ks][mt][0], a[ks][mt][1], a[ks][mt][2], a[ks][mt][3],
                                bb.x, bb.y);
                        mma_f16(acc[mt][2*ntp+1][0], acc[mt][2*ntp+1][1],
                                acc[mt][2*ntp+1][2], acc[mt][2*ntp+1][3],
                                a[ks][mt][0], a[ks][mt][1], a[ks][mt][2], a[ks][mt][3],
                                bb.z, bb.w);
                    }
                }
            }
        }

        // epilogue for this n-half: tanh + dot(u), fixed order
        #pragma unroll
        for (int mt = 0; mt < 2; mt++) {
            #pragma unroll
            for (int nt = 0; nt < 8; nt++) {
                int n = nc * 256 + wn * 64 + nt * 8 + lc * 2;
                float u0 = usm[n], u1 = usm[n + 1];
                float b0 = bsm[n], b1 = bsm[n + 1];
                sp[mt][0] += ftanh(acc[mt][nt][0] + b0) * u0;
                sp[mt][0] += ftanh(acc[mt][nt][1] + b1) * u1;
                sp[mt][1] += ftanh(acc[mt][nt][2] + b0) * u0;
                sp[mt][1] += ftanh(acc[mt][nt][3] + b1) * u1;
            }
        }
    }

    // reduce over 4 lanes sharing a row (fixed order)
    #pragma unroll
    for (int mt = 0; mt < 2; mt++) {
        #pragma unroll
        for (int h = 0; h < 2; h++) {
            sp[mt][h] += __shfl_xor_sync(0xffffffffu, sp[mt][h], 1);
            sp[mt][h] += __shfl_xor_sync(0xffffffffu, sp[mt][h], 2);
        }
    }
    __syncthreads();
    if ((lane & 3) == 0) {
        #pragma unroll
        for (int mt = 0; mt < 2; mt++) {
            int r = wm * 32 + mt * 16 + lr;
            sred[wn * 64 + r]     = sp[mt][0];
            sred[wn * 64 + r + 8] = sp[mt][1];
        }
    }
    __syncthreads();

    if (tid < M_CTA) {
        float s = (sred[tid] + sred[64 + tid]) + (sred[128 + tid] + sred[192 + tid]);
        float e = expf(s);
        se_s[tid] = e;
        sred[tid] = e;
    }
    __syncthreads();
    #pragma unroll
    for (int off = 32; off > 0; off >>= 1) {
        if (tid < off) sred[tid] += sred[tid + off];
        __syncthreads();
    }
    if (tid == 0) g_part[blockIdx.x] = sred[0];

    // pooling partial from f16 A smem
    {
        float p0 = 0.f, p1 = 0.f;
        #pragma unroll 4
        for (int r = 0; r < M_CTA; r++) {
            uint32_t hw = As[r * 256 + (tid ^ ((r & 7) << 2))];
            float2 xf = __half22float2(*(__half2*)&hw);
            float ev = se_s[r];
            p0 += xf.x * ev;
            p1 += xf.y * ev;
        }
        float2* po = (float2*)(g_po + (size_t)blockIdx.x * FEAT);
        po[tid] = make_float2(p0, p1);
    }
}

// ---------------- k4: global-sum + combine + normalize ----------------
// grid (16, BATCH), 128 threads. Every block redundantly reduces g_part
// (identical fixed order -> deterministic). 4 threads cooperate per feature.
__global__ __launch_bounds__(128)
void k4_final(float* __restrict__ out) {
    __shared__ float red[128];
    __shared__ float pos[128];
    const int tid = threadIdx.x;
    const int b = blockIdx.y, q = blockIdx.x;   // q 0..15

    float v = 0.0f;
    #pragma unroll
    for (int i = 0; i < 8; i++)
        v += g_part[tid * 8 + i];
    red[tid] = v;
    __syncthreads();
    #pragma unroll
    for (int off = 64; off > 0; off >>= 1) {
        if (tid < off) red[tid] += red[tid + off];
        __syncthreads();
    }
    const float denom = red[0] + 1e-7f;

    const int ft = tid >> 2, ci = tid & 3;
    const int f = q * 32 + ft;
    float s = 0.0f;
    #pragma unroll
    for (int i = 0; i < 16; i++) {
        int c = ci * 16 + i;
        s += g_po[(size_t)(b * 64 + c) * FEAT + f];
    }
    pos[tid] = s;
    __syncthreads();
    if (ci == 0) {
        float tot = ((pos[tid] + pos[tid + 1]) + pos[tid + 2]) + pos[tid + 3];
        out[b * FEAT + f] = tot / denom;
    }
}

extern "C" void kernel_launch(void* const* d_in, const int* in_sizes, int n_in,
                              void* d_out, int out_size) {
    const float* x = (const float*)d_in[0];
    const float* W = (const float*)d_in[1];
    const float* b = (const float*)d_in[2];
    const float* u = (const float*)d_in[3];
    float* out = (float*)d_out;

    cudaFuncSetAttribute(k1_gemm, cudaFuncAttributeMaxDynamicSharedMemorySize, SMEM_TOTAL);

    k0_pack<<<64, 256>>>(W);
    k1_gemm<<<NUM_CTAS, THREADS, SMEM_TOTAL>>>(x, b, u);
    k4_final<<<dim3(16, BATCH), 128>>>(out);
}

// round 15
// speedup vs baseline: 1.9871x; 1.1604x over previous
#include <cuda_runtime.h>
#include <cuda_fp16.h>
#include <stdint.h>

// ---------------- problem constants ----------------
#define BATCH 16
#define SEQ   4096
#define FEAT  512
#define MROWS (BATCH*SEQ)          // 65536
#define M_CTA 64
#define NUM_CTAS (MROWS/M_CTA)     // 1024
#define THREADS 256
#define NKT 16                     // K slices of 32
#define NC 2                       // N halves of 256
#define NIT (NKT*NC)               // 32

#define A_BYTES   65536            // 64 rows x 512 f16 (1024B/row, XOR-swizzled)

// smem layout (bytes)
#define OFF_U    0                 // 2048
#define OFF_BV   2048              // 2048
#define OFF_SRED 4096              // 4*64 floats = 1024
#define OFF_SE   5120              // 64 floats = 256
#define OFF_A    5376              // 65536
#define SMEM_TOTAL (OFF_A + A_BYTES)   // 70912 (x2 CTAs = 141824)

// ---------------- global scratch ----------------
__device__ uint4  g_Wfrag[32768];              // f16 fragment-major W (512 KB)
__device__ float  g_part[NUM_CTAS];
__device__ float  g_po[(size_t)NUM_CTAS*FEAT];

__device__ __forceinline__ uint32_t pack_f16x2(float lo, float hi) {
    __half2 h = __floats2half2_rn(lo, hi);
    return *(uint32_t*)&h;
}

__device__ __forceinline__ void mma_f16(float& d0, float& d1, float& d2, float& d3,
                                        uint32_t a0, uint32_t a1, uint32_t a2, uint32_t a3,
                                        uint32_t b0, uint32_t b1) {
    asm volatile(
        "mma.sync.aligned.m16n8k16.row.col.f32.f16.f16.f32 "
        "{%0,%1,%2,%3}, {%4,%5,%6,%7}, {%8,%9}, {%0,%1,%2,%3};"
        : "+f"(d0), "+f"(d1), "+f"(d2), "+f"(d3)
        : "r"(a0), "r"(a1), "r"(a2), "r"(a3), "r"(b0), "r"(b1));
}

__device__ __forceinline__ void ldsm_x4(uint32_t& r0, uint32_t& r1, uint32_t& r2, uint32_t& r3,
                                        uint32_t addr) {
    asm volatile("ldmatrix.sync.aligned.m8n8.x4.shared.b16 {%0,%1,%2,%3}, [%4];"
                 : "=r"(r0), "=r"(r1), "=r"(r2), "=r"(r3) : "r"(addr));
}

__device__ __forceinline__ uint32_t smem_u32(const void* p) {
    uint32_t a;
    asm("{ .reg .u64 t; cvta.to.shared.u64 t, %1; cvt.u32.u64 %0, t; }" : "=r"(a) : "l"(p));
    return a;
}

// fast tanh via 2 MUFU; rel err ~1e-6, saturates to +-1
__device__ __forceinline__ float ftanh(float v) {
    float t = __expf(2.0f * v);
    return 1.0f - __fdividef(2.0f, t + 1.0f);
}

// ---------------- k0: pack W -> f16 fragment-major (R13-measured variant) ----------------
// uint4 g[idx], idx = ((kt*2+nc)*32 + ks*16 + wn*4 + ntp)*32 + lane  (32768 total)
__global__ void k0_pack(const float* __restrict__ W) {
    int g = blockIdx.x * 256 + threadIdx.x;          // 0..32767
    int lane = g & 31;
    int t    = g >> 5;
    int ntp  = t & 3;
    int wn   = (t >> 2) & 3;
    int ks   = (t >> 4) & 1;
    int nc   = (t >> 5) & 1;
    int kt   = t >> 6;
    int k   = kt * 32 + ks * 16 + 2 * (lane & 3);
    int np0 = nc * 256 + wn * 64 + ntp * 16 + (lane >> 2);
    int np1 = np0 + 8;
    uint4 v;
    v.x = pack_f16x2(W[(size_t)k * FEAT + np0],       W[(size_t)(k + 1) * FEAT + np0]);
    v.y = pack_f16x2(W[(size_t)(k + 8) * FEAT + np0], W[(size_t)(k + 9) * FEAT + np0]);
    v.z = pack_f16x2(W[(size_t)k * FEAT + np1],       W[(size_t)(k + 1) * FEAT + np1]);
    v.w = pack_f16x2(W[(size_t)(k + 8) * FEAT + np1], W[(size_t)(k + 9) * FEAT + np1]);
    g_Wfrag[g] = v;
}

// ---------------- k1: A-resident, barrier-free K-loop, B direct from L1/L2 ----------------
__global__ __launch_bounds__(THREADS, 2)
void k1_gemm(const float* __restrict__ xg, const float* __restrict__ bg,
             const float* __restrict__ ug) {
    extern __shared__ char smem[];
    const uint32_t sbase = smem_u32(smem);
    const int tid  = threadIdx.x;
    const int lane = tid & 31;
    const int wid  = tid >> 5;
    const int wm   = wid & 1;        // 2 row groups of 32
    const int wn   = wid >> 1;       // 4 col groups of 64 (within 256-half)
    const int lr   = lane >> 2;
    const int lc   = lane & 3;
    const int row0 = blockIdx.x * M_CTA;

    float* usm  = (float*)(smem + OFF_U);
    float* bsm  = (float*)(smem + OFF_BV);
    float* sred = (float*)(smem + OFF_SRED);
    float* se_s = (float*)(smem + OFF_SE);

    #pragma unroll
    for (int i = 0; i < 2; i++) {
        usm[tid + i * THREADS] = ug[tid + i * THREADS];
        bsm[tid + i * THREADS] = bg[tid + i * THREADS];
    }

    // ---- A prologue: load 64x512 fp32 x-tile, convert to f16 smem (XOR swizzle) ----
    // word layout: row r (256 words), word w stored at w ^ ((r&7)<<2)
    {
        uint32_t* As = (uint32_t*)(smem + OFF_A);
        #pragma unroll
        for (int i = 0; i < 32; i++) {
            int id = tid + i * THREADS;       // float4 index, 0..8191
            int r  = id >> 7;
            int c4 = id & 127;
            float4 v = *(const float4*)(xg + (size_t)(row0 + r) * FEAT + c4 * 4);
            int w0 = c4 * 2;
            int sw = w0 ^ ((r & 7) << 2);
            As[r * 256 + sw]     = pack_f16x2(v.x, v.y);
            As[r * 256 + sw + 1] = pack_f16x2(v.z, v.w);
        }
    }
    __syncthreads();        // A visible to all warps; K-loop below is barrier-free

    // ldmatrix per-lane address components
    const int j    = lane >> 3;
    const int rj   = lane & 7;
    const int rowj = wm * 32 + (j & 1) * 8 + rj;
    const int cj   = (j >> 1) * 4;
    const int sj   = rj << 2;
    const uint32_t A0 = sbase + OFF_A;

    float sp[2][2] = {{0.f, 0.f}, {0.f, 0.f}};
    const uint32_t* As = (const uint32_t*)(smem + OFF_A);

    for (int nc = 0; nc < NC; nc++) {
        float acc[2][8][4];
        #pragma unroll
        for (int mt = 0; mt < 2; mt++)
            #pragma unroll
            for (int nt = 0; nt < 8; nt++)
                acc[mt][nt][0] = acc[mt][nt][1] = acc[mt][nt][2] = acc[mt][nt][3] = 0.0f;

        for (int kt = 0; kt < NKT; kt++) {
            // B fragments straight from global (L1-cached; coalesced 512B/instr)
            const uint4* __restrict__ Bf = g_Wfrag + (size_t)(kt * 2 + nc) * 1024;
            uint4 bb[8];
            #pragma unroll
            for (int ks = 0; ks < 2; ks++)
                #pragma unroll
                for (int ntp = 0; ntp < 4; ntp++)
                    bb[ks * 4 + ntp] =
                        __ldg(Bf + (size_t)((ks * 16 + wn * 4 + ntp) * 32 + lane));

            const uint32_t wordbase = rowj * 256 + (((kt * 16) | cj) ^ sj);

            #pragma unroll
            for (int ks = 0; ks < 2; ks++) {
                const uint32_t wks = wordbase ^ (ks << 3);
                uint32_t a[2][4];
                #pragma unroll
                for (int mt = 0; mt < 2; mt++)
                    ldsm_x4(a[mt][0], a[mt][1], a[mt][2], a[mt][3],
                            A0 + mt * 16384 + (wks << 2));
                #pragma unroll
                for (int ntp = 0; ntp < 4; ntp++) {
                    uint4 b4 = bb[ks * 4 + ntp];
                    #pragma unroll
                    for (int mt = 0; mt < 2; mt++) {
                        mma_f16(acc[mt][2*ntp][0], acc[mt][2*ntp][1],
                                acc[mt][2*ntp][2], acc[mt][2*ntp][3],
                                a[mt][0], a[mt][1], a[mt][2], a[mt][3], b4.x, b4.y);
                        mma_f16(acc[mt][2*ntp+1][0], acc[mt][2*ntp+1][1],
                                acc[mt][2*ntp+1][2], acc[mt][2*ntp+1][3],
                                a[mt][0], a[mt][1], a[mt][2], a[mt][3], b4.z, b4.w);
                    }
                }
            }
        }

        // epilogue for this n-half: tanh + dot(u), fixed order
        #pragma unroll
        for (int mt = 0; mt < 2; mt++) {
            #pragma unroll
            for (int nt = 0; nt < 8; nt++) {
                int n = nc * 256 + wn * 64 + nt * 8 + lc * 2;
                float u0 = usm[n], u1 = usm[n + 1];
                float b0 = bsm[n], b1 = bsm[n + 1];
                sp[mt][0] += ftanh(acc[mt][nt][0] + b0) * u0;
                sp[mt][0] += ftanh(acc[mt][nt][1] + b1) * u1;
                sp[mt][1] += ftanh(acc[mt][nt][2] + b0) * u0;
                sp[mt][1] += ftanh(acc[mt][nt][3] + b1) * u1;
            }
        }
    }

    // reduce over 4 lanes sharing a row (fixed order)
    #pragma unroll
    for (int mt = 0; mt < 2; mt++) {
        #pragma unroll
        for (int h = 0; h < 2; h++) {
            sp[mt][h] += __shfl_xor_sync(0xffffffffu, sp[mt][h], 1);
            sp[mt][h] += __shfl_xor_sync(0xffffffffu, sp[mt][h], 2);
        }
    }
    __syncthreads();
    if ((lane & 3) == 0) {
        #pragma unroll
        for (int mt = 0; mt < 2; mt++) {
            int r = wm * 32 + mt * 16 + lr;
            sred[wn * 64 + r]     = sp[mt][0];
            sred[wn * 64 + r + 8] = sp[mt][1];
        }
    }
    __syncthreads();

    if (tid < M_CTA) {
        float s = (sred[tid] + sred[64 + tid]) + (sred[128 + tid] + sred[192 + tid]);
        float e = expf(s);
        se_s[tid] = e;
        sred[tid] = e;
    }
    __syncthreads();
    #pragma unroll
    for (int off = 32; off > 0; off >>= 1) {
        if (tid < off) sred[tid] += sred[tid + off];
        __syncthreads();
    }
    if (tid == 0) g_part[blockIdx.x] = sred[0];

    // pooling partial from f16 A smem
    {
        float p0 = 0.f, p1 = 0.f;
        #pragma unroll 4
        for (int r = 0; r < M_CTA; r++) {
            uint32_t hw = As[r * 256 + (tid ^ ((r & 7) << 2))];
            float2 xf = __half22float2(*(__half2*)&hw);
            float ev = se_s[r];
            p0 += xf.x * ev;
            p1 += xf.y * ev;
        }
        float2* po = (float2*)(g_po + (size_t)blockIdx.x * FEAT);
        po[tid] = make_float2(p0, p1);
    }
}

// ---------------- k4: global-sum + combine + normalize ----------------
// grid (16, BATCH), 128 threads. Every block redundantly reduces g_part
// (identical fixed order -> deterministic). 4 threads cooperate per feature.
__global__ __launch_bounds__(128)
void k4_final(float* __restrict__ out) {
    __shared__ float red[128];
    __shared__ float pos[128];
    const int tid = threadIdx.x;
    const int b = blockIdx.y, q = blockIdx.x;   // q 0..15

    float v = 0.0f;
    #pragma unroll
    for (int i = 0; i < 8; i++)
        v += g_part[tid * 8 + i];
    red[tid] = v;
    __syncthreads();
    #pragma unroll
    for (int off = 64; off > 0; off >>= 1) {
        if (tid < off) red[tid] += red[tid + off];
        __syncthreads();
    }
    const float denom = red[0] + 1e-7f;

    const int ft = tid >> 2, ci = tid & 3;
    const int f = q * 32 + ft;
    float s = 0.0f;
    #pragma unroll
    for (int i = 0; i < 16; i++) {
        int c = ci * 16 + i;
        s += g_po[(size_t)(b * 64 + c) * FEAT + f];
    }
    pos[tid] = s;
    __syncthreads();
    if (ci == 0) {
        float tot = ((pos[tid] + pos[tid + 1]) + pos[tid + 2]) + pos[tid + 3];
        out[b * FEAT + f] = tot / denom;
    }
}

extern "C" void kernel_launch(void* const* d_in, const int* in_sizes, int n_in,
                              void* d_out, int out_size) {
    const float* x = (const float*)d_in[0];
    const float* W = (const float*)d_in[1];
    const float* b = (const float*)d_in[2];
    const float* u = (const float*)d_in[3];
    float* out = (float*)d_out;

    cudaFuncSetAttribute(k1_gemm, cudaFuncAttributeMaxDynamicSharedMemorySize, SMEM_TOTAL);

    k0_pack<<<128, 256>>>(W);
    k1_gemm<<<NUM_CTAS, THREADS, SMEM_TOTAL>>>(x, b, u);
    k4_final<<<dim3(16, BATCH), 128>>>(out);
}

// round 16
// speedup vs baseline: 2.0119x; 1.0125x over previous
#include <cuda_runtime.h>
#include <cuda_fp16.h>
#include <stdint.h>

// ---------------- problem constants ----------------
#define BATCH 16
#define SEQ   4096
#define FEAT  512
#define MROWS (BATCH*SEQ)          // 65536
#define M_CTA 64
#define NUM_CTAS (MROWS/M_CTA)     // 1024
#define THREADS 256
#define NKT 16                     // K slices of 32
#define NCH 4                      // N chunks of 128

#define A_BYTES   65536            // 64 rows x 512 f16 (1024B/row, XOR-swizzled)

// smem layout (bytes)
#define OFF_U    0                 // 2048
#define OFF_BV   2048              // 2048
#define OFF_SRED 4096              // 4*64 floats = 1024
#define OFF_SE   5120              // 64 floats = 256
#define OFF_A    5376              // 65536
#define SMEM_TOTAL (OFF_A + A_BYTES)   // 70912 (x2 CTAs = 141824)

// ---------------- global scratch ----------------
__device__ uint4  g_Wfrag[32768];              // f16 fragment-major W (512 KB)
__device__ float  g_part[NUM_CTAS];
__device__ float  g_po[(size_t)NUM_CTAS*FEAT];

__device__ __forceinline__ uint32_t pack_f16x2(float lo, float hi) {
    __half2 h = __floats2half2_rn(lo, hi);
    return *(uint32_t*)&h;
}

__device__ __forceinline__ void mma_f16(float& d0, float& d1, float& d2, float& d3,
                                        uint32_t a0, uint32_t a1, uint32_t a2, uint32_t a3,
                                        uint32_t b0, uint32_t b1) {
    asm volatile(
        "mma.sync.aligned.m16n8k16.row.col.f32.f16.f16.f32 "
        "{%0,%1,%2,%3}, {%4,%5,%6,%7}, {%8,%9}, {%0,%1,%2,%3};"
        : "+f"(d0), "+f"(d1), "+f"(d2), "+f"(d3)
        : "r"(a0), "r"(a1), "r"(a2), "r"(a3), "r"(b0), "r"(b1));
}

__device__ __forceinline__ void ldsm_x4(uint32_t& r0, uint32_t& r1, uint32_t& r2, uint32_t& r3,
                                        uint32_t addr) {
    asm volatile("ldmatrix.sync.aligned.m8n8.x4.shared.b16 {%0,%1,%2,%3}, [%4];"
                 : "=r"(r0), "=r"(r1), "=r"(r2), "=r"(r3) : "r"(addr));
}

__device__ __forceinline__ uint32_t smem_u32(const void* p) {
    uint32_t a;
    asm("{ .reg .u64 t; cvta.to.shared.u64 t, %1; cvt.u32.u64 %0, t; }" : "=r"(a) : "l"(p));
    return a;
}

// fast tanh via 2 MUFU; rel err ~1e-6, saturates to +-1
__device__ __forceinline__ float ftanh(float v) {
    float t = __expf(2.0f * v);
    return 1.0f - __fdividef(2.0f, t + 1.0f);
}

// ---------------- k0: pack W -> f16 fragment-major (R13-measured variant) ----------------
// uint4 g[idx], idx = ((kt*2+nc)*32 + ks*16 + wno*4 + ntpo)*32 + lane  (32768 total)
__global__ void k0_pack(const float* __restrict__ W) {
    int g = blockIdx.x * 256 + threadIdx.x;          // 0..32767
    int lane = g & 31;
    int t    = g >> 5;
    int ntp  = t & 3;
    int wn   = (t >> 2) & 3;
    int ks   = (t >> 4) & 1;
    int nc   = (t >> 5) & 1;
    int kt   = t >> 6;
    int k   = kt * 32 + ks * 16 + 2 * (lane & 3);
    int np0 = nc * 256 + wn * 64 + ntp * 16 + (lane >> 2);
    int np1 = np0 + 8;
    uint4 v;
    v.x = pack_f16x2(W[(size_t)k * FEAT + np0],       W[(size_t)(k + 1) * FEAT + np0]);
    v.y = pack_f16x2(W[(size_t)(k + 8) * FEAT + np0], W[(size_t)(k + 9) * FEAT + np0]);
    v.z = pack_f16x2(W[(size_t)k * FEAT + np1],       W[(size_t)(k + 1) * FEAT + np1]);
    v.w = pack_f16x2(W[(size_t)(k + 8) * FEAT + np1], W[(size_t)(k + 9) * FEAT + np1]);
    g_Wfrag[g] = v;
}

// B fragment gather for (global-iter git, warp wn, lane): 4 uint4
// git = c*16 + kt; chunk c covers cols [c*128, +128); warp covers 32 cols.
// Maps onto the packed layout via wno=(c&1)*2+(wn>>1), ntpo=(wn&1)*2+ntp.
__device__ __forceinline__ void ldg_B(uint4 bb[4], int git, int wn, int lane) {
    const int c = git >> 4, kt = git & 15;
    const uint4* __restrict__ slab = g_Wfrag + (size_t)(kt * 2 + (c >> 1)) * 1024;
    const int wno = (c & 1) * 2 + (wn >> 1);
    const int base = wno * 4 + (wn & 1) * 2;
    #pragma unroll
    for (int ks = 0; ks < 2; ks++)
        #pragma unroll
        for (int ntp = 0; ntp < 2; ntp++)
            bb[ks * 2 + ntp] = __ldg(slab + (size_t)((ks * 16 + base + ntp) * 32 + lane));
}

// ---------------- k1: A-resident, barrier-free, B prefetched 1 iter ahead ----------------
__global__ __launch_bounds__(THREADS, 2)
void k1_gemm(const float* __restrict__ xg, const float* __restrict__ bg,
             const float* __restrict__ ug) {
    extern __shared__ char smem[];
    const uint32_t sbase = smem_u32(smem);
    const int tid  = threadIdx.x;
    const int lane = tid & 31;
    const int wid  = tid >> 5;
    const int wm   = wid & 1;        // 2 row groups of 32
    const int wn   = wid >> 1;       // 4 col groups of 32 (within 128-chunk)
    const int lr   = lane >> 2;
    const int lc   = lane & 3;
    const int row0 = blockIdx.x * M_CTA;

    float* usm  = (float*)(smem + OFF_U);
    float* bsm  = (float*)(smem + OFF_BV);
    float* sred = (float*)(smem + OFF_SRED);
    float* se_s = (float*)(smem + OFF_SE);

    #pragma unroll
    for (int i = 0; i < 2; i++) {
        usm[tid + i * THREADS] = ug[tid + i * THREADS];
        bsm[tid + i * THREADS] = bg[tid + i * THREADS];
    }

    // ---- A prologue: load 64x512 fp32 x-tile, convert to f16 smem (XOR swizzle) ----
    {
        uint32_t* As = (uint32_t*)(smem + OFF_A);
        #pragma unroll
        for (int i = 0; i < 32; i++) {
            int id = tid + i * THREADS;       // float4 index, 0..8191
            int r  = id >> 7;
            int c4 = id & 127;
            float4 v = *(const float4*)(xg + (size_t)(row0 + r) * FEAT + c4 * 4);
            int w0 = c4 * 2;
            int sw = w0 ^ ((r & 7) << 2);
            As[r * 256 + sw]     = pack_f16x2(v.x, v.y);
            As[r * 256 + sw + 1] = pack_f16x2(v.z, v.w);
        }
    }
    __syncthreads();        // A visible to all warps; K-loop below is barrier-free

    // ldmatrix per-lane address components
    const int j    = lane >> 3;
    const int rj   = lane & 7;
    const int rowj = wm * 32 + (j & 1) * 8 + rj;
    const int cj   = (j >> 1) * 4;
    const int sj   = rj << 2;
    const uint32_t A0 = sbase + OFF_A;

    float sp[2][2] = {{0.f, 0.f}, {0.f, 0.f}};
    const uint32_t* As = (const uint32_t*)(smem + OFF_A);

    // B ping-pong buffers; prefetch git=0
    uint4 bbA[4], bbB[4];
    ldg_B(bbA, 0, wn, lane);

    for (int c = 0; c < NCH; c++) {
        float acc[2][4][4];
        #pragma unroll
        for (int mt = 0; mt < 2; mt++)
            #pragma unroll
            for (int nt = 0; nt < 4; nt++)
                acc[mt][nt][0] = acc[mt][nt][1] = acc[mt][nt][2] = acc[mt][nt][3] = 0.0f;

        #pragma unroll
        for (int kt = 0; kt < NKT; kt++) {
            const int git = c * NKT + kt;
            uint4* cur = (git & 1) ? bbB : bbA;
            uint4* nxt = (git & 1) ? bbA : bbB;

            // prefetch next iteration's B (covered by LDSM + 16 MMAs below)
            if (git + 1 < NCH * NKT) ldg_B(nxt, git + 1, wn, lane);

            // A fragments for this kt (both ks halves)
            const uint32_t wordbase = rowj * 256 + (((kt * 16) | cj) ^ sj);
            uint32_t a[2][2][4];   // [ks][mt][4]
            #pragma unroll
            for (int ks = 0; ks < 2; ks++) {
                const uint32_t wks = wordbase ^ (ks << 3);
                #pragma unroll
                for (int mt = 0; mt < 2; mt++)
                    ldsm_x4(a[ks][mt][0], a[ks][mt][1], a[ks][mt][2], a[ks][mt][3],
                            A0 + mt * 16384 + (wks << 2));
            }

            #pragma unroll
            for (int ks = 0; ks < 2; ks++) {
                #pragma unroll
                for (int ntp = 0; ntp < 2; ntp++) {
                    uint4 b4 = cur[ks * 2 + ntp];
                    #pragma unroll
                    for (int mt = 0; mt < 2; mt++) {
                        mma_f16(acc[mt][2*ntp][0], acc[mt][2*ntp][1],
                                acc[mt][2*ntp][2], acc[mt][2*ntp][3],
                                a[ks][mt][0], a[ks][mt][1], a[ks][mt][2], a[ks][mt][3],
                                b4.x, b4.y);
                        mma_f16(acc[mt][2*ntp+1][0], acc[mt][2*ntp+1][1],
                                acc[mt][2*ntp+1][2], acc[mt][2*ntp+1][3],
                                a[ks][mt][0], a[ks][mt][1], a[ks][mt][2], a[ks][mt][3],
                                b4.z, b4.w);
                    }
                }
            }
        }

        // epilogue for this 128-chunk: tanh + dot(u), fixed order
        #pragma unroll
        for (int mt = 0; mt < 2; mt++) {
            #pragma unroll
            for (int nt = 0; nt < 4; nt++) {
                int n = c * 128 + wn * 32 + nt * 8 + lc * 2;
                float u0 = usm[n], u1 = usm[n + 1];
                float b0 = bsm[n], b1 = bsm[n + 1];
                sp[mt][0] += ftanh(acc[mt][nt][0] + b0) * u0;
                sp[mt][0] += ftanh(acc[mt][nt][1] + b1) * u1;
                sp[mt][1] += ftanh(acc[mt][nt][2] + b0) * u0;
                sp[mt][1] += ftanh(acc[mt][nt][3] + b1) * u1;
            }
        }
    }

    // reduce over 4 lanes sharing a row (fixed order)
    #pragma unroll
    for (int mt = 0; mt < 2; mt++) {
        #pragma unroll
        for (int h = 0; h < 2; h++) {
            sp[mt][h] += __shfl_xor_sync(0xffffffffu, sp[mt][h], 1);
            sp[mt][h] += __shfl_xor_sync(0xffffffffu, sp[mt][h], 2);
        }
    }
    __syncthreads();
    if ((lane & 3) == 0) {
        #pragma unroll
        for (int mt = 0; mt < 2; mt++) {
            int r = wm * 32 + mt * 16 + lr;
            sred[wn * 64 + r]     = sp[mt][0];
            sred[wn * 64 + r + 8] = sp[mt][1];
        }
    }
    __syncthreads();

    if (tid < M_CTA) {
        float s = (sred[tid] + sred[64 + tid]) + (sred[128 + tid] + sred[192 + tid]);
        float e = expf(s);
        se_s[tid] = e;
        sred[tid] = e;
    }
    __syncthreads();
    #pragma unroll
    for (int off = 32; off > 0; off >>= 1) {
        if (tid < off) sred[tid] += sred[tid + off];
        __syncthreads();
    }
    if (tid == 0) g_part[blockIdx.x] = sred[0];

    // pooling partial from f16 A smem
    {
        float p0 = 0.f, p1 = 0.f;
        #pragma unroll 4
        for (int r = 0; r < M_CTA; r++) {
            uint32_t hw = As[r * 256 + (tid ^ ((r & 7) << 2))];
            float2 xf = __half22float2(*(__half2*)&hw);
            float ev = se_s[r];
            p0 += xf.x * ev;
            p1 += xf.y * ev;
        }
        float2* po = (float2*)(g_po + (size_t)blockIdx.x * FEAT);
        po[tid] = make_float2(p0, p1);
    }
}

// ---------------- k4: global-sum + combine + normalize ----------------
__global__ __launch_bounds__(128)
void k4_final(float* __restrict__ out) {
    __shared__ float red[128];
    __shared__ float pos[128];
    const int tid = threadIdx.x;
    const int b = blockIdx.y, q = blockIdx.x;   // q 0..15

    float v = 0.0f;
    #pragma unroll
    for (int i = 0; i < 8; i++)
        v += g_part[tid * 8 + i];
    red[tid] = v;
    __syncthreads();
    #pragma unroll
    for (int off = 64; off > 0; off >>= 1) {
        if (tid < off) red[tid] += red[tid + off];
        __syncthreads();
    }
    const float denom = red[0] + 1e-7f;

    const int ft = tid >> 2, ci = tid & 3;
    const int f = q * 32 + ft;
    float s = 0.0f;
    #pragma unroll
    for (int i = 0; i < 16; i++) {
        int c = ci * 16 + i;
        s += g_po[(size_t)(b * 64 + c) * FEAT + f];
    }
    pos[tid] = s;
    __syncthreads();
    if (ci == 0) {
        float tot = ((pos[tid] + pos[tid + 1]) + pos[tid + 2]) + pos[tid + 3];
        out[b * FEAT + f] = tot / denom;
    }
}

extern "C" void kernel_launch(void* const* d_in, const int* in_sizes, int n_in,
                              void* d_out, int out_size) {
    const float* x = (const float*)d_in[0];
    const float* W = (const float*)d_in[1];
    const float* b = (const float*)d_in[2];
    const float* u = (const float*)d_in[3];
    float* out = (float*)d_out;

    cudaFuncSetAttribute(k1_gemm, cudaFuncAttributeMaxDynamicSharedMemorySize, SMEM_TOTAL);

    k0_pack<<<128, 256>>>(W);
    k1_gemm<<<NUM_CTAS, THREADS, SMEM_TOTAL>>>(x, b, u);
    k4_final<<<dim3(16, BATCH), 128>>>(out);
}